// round 9
// baseline (speedup 1.0000x reference)
#include <cuda_runtime.h>

#define S_TOK     2304
#define D_MODEL   3072
#define NHEAD     24
#define HDIM      128
#define BLOCK_TOK 2048
#define CONDN     256
#define RANKN     128
#define T_IPN     128
#define D_IPN     4096
#define EPSV      1e-5f
// (1/sqrt(128)) * log2(e): softmax computed in exp2 domain
#define QSCALE    0.1275173e+0f
#define BIGROW    0x7fffffff

// ---------------- device scratch ----------------
__device__ float g_q[S_TOK * D_MODEL];
__device__ float g_k[S_TOK * D_MODEL];
__device__ float g_vt[D_MODEL * S_TOK];     // V transposed: [d 3072][tok 2304]
__device__ float g_kip[T_IPN * D_MODEL];
__device__ float g_vipt[D_MODEL * T_IPN];   // V_ip transposed
__device__ float g_lt[3 * CONDN * RANKN];
__device__ float g_xr[S_TOK * D_MODEL];     // RNA-tf32-rounded A-side operands
__device__ float g_imgr[T_IPN * D_IPN];

// ---------------- helpers ----------------
__device__ __forceinline__ unsigned f2tf(float f) {
    unsigned u;
    asm("cvt.rna.tf32.f32 %0, %1;" : "=r"(u) : "f"(f));
    return u;
}
__device__ __forceinline__ void mma8(float* c, const unsigned* a, unsigned b0, unsigned b1) {
    asm volatile(
        "mma.sync.aligned.m16n8k8.row.col.f32.tf32.tf32.f32 "
        "{%0,%1,%2,%3}, {%4,%5,%6,%7}, {%8,%9}, {%0,%1,%2,%3};"
        : "+f"(c[0]), "+f"(c[1]), "+f"(c[2]), "+f"(c[3])
        : "r"(a[0]), "r"(a[1]), "r"(a[2]), "r"(a[3]), "r"(b0), "r"(b1));
}
__device__ __forceinline__ void cpa16(unsigned dst, const void* src) {
    asm volatile("cp.async.cg.shared.global [%0], [%1], 16;" :: "r"(dst), "l"(src));
}
__device__ __forceinline__ void cp_commit() { asm volatile("cp.async.commit_group;"); }
__device__ __forceinline__ void cp_wait0() { asm volatile("cp.async.wait_group 0;"); }
__device__ __forceinline__ void cp_wait1() { asm volatile("cp.async.wait_group 1;"); }

// ---------------- RNA tf32 rounding pre-pass (A-side only) ----------------
struct R2 { const float* s[2]; float* d[2]; int n[2]; };
__global__ void round_tf32_kernel(R2 P) {
    const int y = blockIdx.y;
    const float4* src = (const float4*)P.s[y];
    float4* dst = (float4*)P.d[y];
    const int n4 = P.n[y] >> 2;
    for (int i = blockIdx.x * blockDim.x + threadIdx.x; i < n4; i += gridDim.x * blockDim.x) {
        float4 v = src[i];
        v.x = __uint_as_float(f2tf(v.x));
        v.y = __uint_as_float(f2tf(v.y));
        v.z = __uint_as_float(f2tf(v.z));
        v.w = __uint_as_float(f2tf(v.w));
        dst[i] = v;
    }
}

// ============ batched GEMM (A pre-rounded, B cvt-in-loop, fused norm epilogue) ============
// C[M,N] (+)= A[M,K] @ B[N,K]^T + bias. 128x128 tile, BK=16, 256 thr, warp tile
// 64x32, 3-stage cp.async (1 sync/slab), smem [mn][k] stride 20.
// nrm: 0 raw, 1 round, 2 norm+round, 3 norm+w+rope+round, 4 = 3 + QSCALE.
// rows >= rowlim stored raw. tr: store/ACC C transposed as C[col][ldt] at row stoff+r.
struct GemmB {
    const float* A[8]; const float* Bm[8]; const float* bias[8]; float* C[8];
    const float* w[8];
    int M[8], N[8], K[8], nrm[8], rowlim[8], tokoff[8], tr[8], ldt[8], stoff[8];
};

template <bool ACC>
__global__ __launch_bounds__(256, 2) void gemm_tc(GemmB P, const float* cs, const float* sn)
{
    extern __shared__ unsigned smg[];
    unsigned* As = smg;              // 3 stages x 2560
    unsigned* Bs = smg + 3 * 2560;   // 3 stages x 2560

    const int z = blockIdx.z;
    const int M = P.M[z], N = P.N[z], K = P.K[z];
    const int bm = blockIdx.y << 7, bn = blockIdx.x << 7;
    if (bm >= M || bn >= N) return;
    const float* A = P.A[z];
    const float* Bw = P.Bm[z];
    const float* bias = P.bias[z];
    float* C = P.C[z];
    const float* wp = P.w[z];
    const int mode = (bm >= P.rowlim[z]) ? 0 : P.nrm[z];
    const int tokoff = P.tokoff[z];
    const int tr = P.tr[z], ldt = P.ldt[z], stoff = P.stoff[z];

    const int tid = threadIdx.x;
    const int lw = tid & 31, w = tid >> 5, g = lw >> 2, t = lw & 3;
    const int wm = w & 1, wn = w >> 1;   // 2 x 4 warp grid, warp tile 64x32

    const int lrow = tid >> 1, lseg = (tid & 1) * 8;
    const float* Arow = A + (size_t)(bm + lrow) * K + lseg;
    const float* Brow = Bw + (size_t)(bn + lrow) * K + lseg;
    const unsigned as_u = (unsigned)__cvta_generic_to_shared(As) + (lrow * 20 + lseg) * 4;
    const unsigned bs_u = (unsigned)__cvta_generic_to_shared(Bs) + (lrow * 20 + lseg) * 4;

    float acc[4][4][4];
#pragma unroll
    for (int mt = 0; mt < 4; mt++)
#pragma unroll
        for (int nt = 0; nt < 4; nt++)
#pragma unroll
            for (int i = 0; i < 4; i++) acc[mt][nt][i] = 0.f;

    const int niter = K >> 4;
    cpa16(as_u, Arow);              cpa16(as_u + 16, Arow + 4);
    cpa16(bs_u, Brow);              cpa16(bs_u + 16, Brow + 4);
    cp_commit();
    {
        const unsigned off = 2560u * 4u;
        cpa16(as_u + off, Arow + 16);   cpa16(as_u + off + 16, Arow + 20);
        cpa16(bs_u + off, Brow + 16);   cpa16(bs_u + off + 16, Brow + 20);
        cp_commit();
    }

    int st = 0, ld = 2;
    for (int it = 0; it < niter; it++) {
        if (it + 1 < niter) cp_wait1(); else cp_wait0();
        __syncthreads();
        if (it + 2 < niter) {
            const int k0 = (it + 2) << 4;
            const unsigned off = (unsigned)(ld * 2560 * 4);
            cpa16(as_u + off, Arow + k0);   cpa16(as_u + off + 16, Arow + k0 + 4);
            cpa16(bs_u + off, Brow + k0);   cpa16(bs_u + off + 16, Brow + k0 + 4);
            cp_commit();
            ld = (ld == 2) ? 0 : ld + 1;
        }
        const unsigned* Ac = As + st * 2560;
        const unsigned* Bc = Bs + st * 2560;
        st = (st == 2) ? 0 : st + 1;
#pragma unroll
        for (int ks = 0; ks < 2; ks++) {
            const int kr = ks * 8 + t;
            unsigned af[4][4], bf[4][2];
#pragma unroll
            for (int mt = 0; mt < 4; mt++) {
                const unsigned* ap = Ac + (wm * 64 + mt * 16 + g) * 20 + kr;
                af[mt][0] = ap[0];
                af[mt][1] = ap[160];
                af[mt][2] = ap[4];
                af[mt][3] = ap[164];
            }
#pragma unroll
            for (int nt = 0; nt < 4; nt++) {
                const float* bp = (const float*)(Bc + (wn * 32 + nt * 8 + g) * 20 + kr);
                bf[nt][0] = f2tf(bp[0]);
                bf[nt][1] = f2tf(bp[4]);
            }
#pragma unroll
            for (int mt = 0; mt < 4; mt++)
#pragma unroll
                for (int nt = 0; nt < 4; nt++)
                    mma8(acc[mt][nt], af[mt], bf[nt][0], bf[nt][1]);
        }
    }

    // ---- epilogue: bias/ACC ----
#pragma unroll
    for (int mt = 0; mt < 4; mt++) {
        const int r0 = bm + wm * 64 + mt * 16 + g;
        const int r1 = r0 + 8;
#pragma unroll
        for (int nt = 0; nt < 4; nt++) {
            const int cc = bn + wn * 32 + nt * 8 + 2 * t;
            if (bias) {
                float bx = bias[cc], by = bias[cc + 1];
                acc[mt][nt][0] += bx; acc[mt][nt][1] += by;
                acc[mt][nt][2] += bx; acc[mt][nt][3] += by;
            }
            if (ACC) {
                if (tr) {
                    acc[mt][nt][0] += C[(size_t)cc * ldt + stoff + r0];
                    acc[mt][nt][1] += C[(size_t)(cc + 1) * ldt + stoff + r0];
                    acc[mt][nt][2] += C[(size_t)cc * ldt + stoff + r1];
                    acc[mt][nt][3] += C[(size_t)(cc + 1) * ldt + stoff + r1];
                } else {
                    float2 e0 = *(const float2*)(C + (size_t)r0 * N + cc);
                    float2 e1 = *(const float2*)(C + (size_t)r1 * N + cc);
                    acc[mt][nt][0] += e0.x; acc[mt][nt][1] += e0.y;
                    acc[mt][nt][2] += e1.x; acc[mt][nt][3] += e1.y;
                }
            }
        }
    }

    float inv0[4], inv1[4];
    if (mode >= 2) {
        __syncthreads();
        float* ssb = (float*)smg;   // [128 rows][4 wn]
#pragma unroll
        for (int mt = 0; mt < 4; mt++) {
            float s0 = 0.f, s1 = 0.f;
#pragma unroll
            for (int nt = 0; nt < 4; nt++) {
                s0 += acc[mt][nt][0] * acc[mt][nt][0] + acc[mt][nt][1] * acc[mt][nt][1];
                s1 += acc[mt][nt][2] * acc[mt][nt][2] + acc[mt][nt][3] * acc[mt][nt][3];
            }
            s0 += __shfl_xor_sync(0xffffffffu, s0, 1);
            s0 += __shfl_xor_sync(0xffffffffu, s0, 2);
            s1 += __shfl_xor_sync(0xffffffffu, s1, 1);
            s1 += __shfl_xor_sync(0xffffffffu, s1, 2);
            if (t == 0) {
                const int rr = wm * 64 + mt * 16 + g;
                ssb[rr * 4 + wn] = s0;
                ssb[(rr + 8) * 4 + wn] = s1;
            }
        }
        __syncthreads();
#pragma unroll
        for (int mt = 0; mt < 4; mt++) {
            const int rr = wm * 64 + mt * 16 + g;
            float4 a = ((const float4*)ssb)[rr];
            float4 b = ((const float4*)ssb)[rr + 8];
            inv0[mt] = rsqrtf((a.x + a.y + a.z + a.w) * (1.0f / HDIM) + EPSV);
            inv1[mt] = rsqrtf((b.x + b.y + b.z + b.w) * (1.0f / HDIM) + EPSV);
        }
    }

#pragma unroll
    for (int mt = 0; mt < 4; mt++) {
        const int r0 = bm + wm * 64 + mt * 16 + g;
        const int r1 = r0 + 8;
#pragma unroll
        for (int nt = 0; nt < 4; nt++) {
            const int d = wn * 32 + nt * 8 + 2 * t;
            const int cc = bn + d;
            float2 v0 = make_float2(acc[mt][nt][0], acc[mt][nt][1]);
            float2 v1 = make_float2(acc[mt][nt][2], acc[mt][nt][3]);
            if (mode >= 2) {
                v0.x *= inv0[mt]; v0.y *= inv0[mt];
                v1.x *= inv1[mt]; v1.y *= inv1[mt];
                if (wp) {
                    float2 ww = *(const float2*)(wp + d);
                    v0.x *= ww.x; v0.y *= ww.y;
                    v1.x *= ww.x; v1.y *= ww.y;
                }
            }
            if (mode >= 3) {
                const size_t t0 = (size_t)(tokoff + r0) * HDIM + d;
                const size_t t1 = (size_t)(tokoff + r1) * HDIM + d;
                float2 c0 = *(const float2*)(cs + t0);
                float2 s0v = *(const float2*)(sn + t0);
                float2 c1 = *(const float2*)(cs + t1);
                float2 s1v = *(const float2*)(sn + t1);
                float e0 = v0.x * c0.x - v0.y * s0v.x;
                float o0 = v0.y * c0.y + v0.x * s0v.y;
                float e1 = v1.x * c1.x - v1.y * s1v.x;
                float o1 = v1.y * c1.y + v1.x * s1v.y;
                v0.x = e0; v0.y = o0; v1.x = e1; v1.y = o1;
            }
            if (mode == 4) {
                v0.x *= QSCALE; v0.y *= QSCALE;
                v1.x *= QSCALE; v1.y *= QSCALE;
            }
            if (mode >= 1) {
                v0.x = __uint_as_float(f2tf(v0.x));
                v0.y = __uint_as_float(f2tf(v0.y));
                v1.x = __uint_as_float(f2tf(v1.x));
                v1.y = __uint_as_float(f2tf(v1.y));
            }
            if (tr) {
                C[(size_t)cc * ldt + stoff + r0] = v0.x;
                C[(size_t)(cc + 1) * ldt + stoff + r0] = v0.y;
                C[(size_t)cc * ldt + stoff + r1] = v1.x;
                C[(size_t)(cc + 1) * ldt + stoff + r1] = v1.y;
            } else {
                *(float2*)(C + (size_t)r0 * N + cc) = v0;
                *(float2*)(C + (size_t)r1 * N + cc) = v1;
            }
        }
    }
}

// ============ flash attention, S^T/O^T form, 2 CTAs/SM ============
// CTA: 256 thr (8 warps), Bq=64 (8 q-cols per warp), Bk=32, K natural [kv][d],
// V pre-transposed [d][tok]. S^T = K Q^T, O^T = V^T P^T. Double-buffered cp.async.
#define KST 4224   // 32*132 words per K stage
#define VST 4608   // 128*36 words per V stage
__global__ __launch_bounds__(256, 2) void attn_tc(
    const unsigned* __restrict__ Q, const unsigned* __restrict__ Km,
    const unsigned* __restrict__ Vtm, const unsigned* __restrict__ Ki,
    const unsigned* __restrict__ Vti, float* __restrict__ Out)
{
    extern __shared__ unsigned smu[];
    unsigned* Ks = smu;                    // [2][32][132]
    unsigned* Vs = smu + 2 * KST;          // [2][128][36]
    unsigned* Ps = smu + 2 * KST + 2 * VST;  // [64 q][36 kv]

    const int tid = threadIdx.x;
    const int l = tid & 31, w = tid >> 5;
    const int g = l >> 2, t = l & 3;
    const int h = blockIdx.y;
    const int q0 = blockIdx.x << 6;

    // Q as B-fragments: qf[ks][0]=Q[q0+w*8+g][ks*8+t], [1]=+4  (pre-scaled, tf32)
    unsigned qf[16][2];
    {
        const unsigned* qp = Q + (size_t)(q0 + w * 8 + g) * D_MODEL + h * HDIM;
#pragma unroll
        for (int ks = 0; ks < 16; ks++) {
            qf[ks][0] = qp[ks * 8 + t];
            qf[ks][1] = qp[ks * 8 + t + 4];
        }
    }

    const int krow = tid >> 3, kseg = (tid & 7) * 16;   // K tile fill
    const int vrow = tid >> 1, vseg = (tid & 1) * 16;   // Vt tile fill
    const unsigned ks_u = (unsigned)__cvta_generic_to_shared(Ks) + (krow * 132 + kseg) * 4;
    const unsigned vs_u = (unsigned)__cvta_generic_to_shared(Vs) + (vrow * 36 + vseg) * 4;

#pragma unroll 1
    for (int ph = 0; ph < 2; ph++) {
        const unsigned* Kb = ph ? Ki : Km;
        const unsigned* Vb = ph ? Vti : Vtm;
        const int toks = ph ? T_IPN : S_TOK;
        const int kt0 = (ph == 0 && q0 >= BLOCK_TOK) ? BLOCK_TOK : 0;
        const int ntiles = (toks - kt0) >> 5;

        float o[8][4];
#pragma unroll
        for (int mt = 0; mt < 8; mt++)
#pragma unroll
            for (int i = 0; i < 4; i++) o[mt][i] = 0.f;
        float m0 = -1e30f, m1 = -1e30f, l0 = 0.f, l1 = 0.f;

        __syncthreads();   // smem free from previous phase
        {
            const unsigned* kg = Kb + (size_t)(kt0 + krow) * D_MODEL + h * HDIM + kseg;
            const unsigned* vg = Vb + (size_t)(h * HDIM + vrow) * toks + kt0 + vseg;
#pragma unroll
            for (int c = 0; c < 4; c++) {
                cpa16(ks_u + c * 16, kg + c * 4);
                cpa16(vs_u + c * 16, vg + c * 4);
            }
            cp_commit();
        }

        for (int it = 0; it < ntiles; it++) {
            const int cur = it & 1;
            cp_wait0();
            __syncthreads();
            if (it + 1 < ntiles) {
                const int kt = kt0 + (it + 1) * 32;
                const unsigned* kg = Kb + (size_t)(kt + krow) * D_MODEL + h * HDIM + kseg;
                const unsigned* vg = Vb + (size_t)(h * HDIM + vrow) * toks + kt + vseg;
                const unsigned ko = ks_u + (cur ^ 1) * KST * 4;
                const unsigned vo = vs_u + (cur ^ 1) * VST * 4;
#pragma unroll
                for (int c = 0; c < 4; c++) {
                    cpa16(ko + c * 16, kg + c * 4);
                    cpa16(vo + c * 16, vg + c * 4);
                }
                cp_commit();
            }
            const unsigned* Kc = Ks + cur * KST;
            const unsigned* Vc = Vs + cur * VST;

            // S^T[kv 32][q 8] = K Q^T
            float s0[4] = {0.f, 0.f, 0.f, 0.f};
            float s1[4] = {0.f, 0.f, 0.f, 0.f};
#pragma unroll
            for (int ks = 0; ks < 16; ks++) {
                const unsigned* ap = Kc + g * 132 + ks * 8 + t;
                unsigned a0[4] = {ap[0], ap[8 * 132], ap[4], ap[8 * 132 + 4]};
                unsigned a1[4] = {ap[16 * 132], ap[24 * 132], ap[16 * 132 + 4], ap[24 * 132 + 4]};
                mma8(s0, a0, qf[ks][0], qf[ks][1]);
                mma8(s1, a1, qf[ks][0], qf[ks][1]);
            }

            // column-wise online softmax (cols q = w*8 + 2t, +1; rows kv)
            float mx0 = fmaxf(fmaxf(s0[0], s0[2]), fmaxf(s1[0], s1[2]));
            float mx1 = fmaxf(fmaxf(s0[1], s0[3]), fmaxf(s1[1], s1[3]));
            mx0 = fmaxf(mx0, __shfl_xor_sync(0xffffffffu, mx0, 4));
            mx0 = fmaxf(mx0, __shfl_xor_sync(0xffffffffu, mx0, 8));
            mx0 = fmaxf(mx0, __shfl_xor_sync(0xffffffffu, mx0, 16));
            mx1 = fmaxf(mx1, __shfl_xor_sync(0xffffffffu, mx1, 4));
            mx1 = fmaxf(mx1, __shfl_xor_sync(0xffffffffu, mx1, 8));
            mx1 = fmaxf(mx1, __shfl_xor_sync(0xffffffffu, mx1, 16));
            const float mn0 = fmaxf(m0, mx0), mn1 = fmaxf(m1, mx1);
            const float al0 = exp2f(m0 - mn0), al1 = exp2f(m1 - mn1);
            m0 = mn0; m1 = mn1;

            float p00 = exp2f(s0[0] - mn0), p02 = exp2f(s0[2] - mn0);
            float p10 = exp2f(s1[0] - mn0), p12 = exp2f(s1[2] - mn0);
            float p01 = exp2f(s0[1] - mn1), p03 = exp2f(s0[3] - mn1);
            float p11 = exp2f(s1[1] - mn1), p13 = exp2f(s1[3] - mn1);
            float sum0 = p00 + p02 + p10 + p12;
            float sum1 = p01 + p03 + p11 + p13;
            sum0 += __shfl_xor_sync(0xffffffffu, sum0, 4);
            sum0 += __shfl_xor_sync(0xffffffffu, sum0, 8);
            sum0 += __shfl_xor_sync(0xffffffffu, sum0, 16);
            sum1 += __shfl_xor_sync(0xffffffffu, sum1, 4);
            sum1 += __shfl_xor_sync(0xffffffffu, sum1, 8);
            sum1 += __shfl_xor_sync(0xffffffffu, sum1, 16);
            l0 = l0 * al0 + sum0;
            l1 = l1 * al1 + sum1;
            if (al0 != 1.f || al1 != 1.f) {
#pragma unroll
                for (int mt = 0; mt < 8; mt++) {
                    o[mt][0] *= al0; o[mt][1] *= al1;
                    o[mt][2] *= al0; o[mt][3] *= al1;
                }
            }
            // store P[q][kv] (warp-private q rows)
            {
                unsigned* Pr0 = Ps + (w * 8 + 2 * t) * 36;
                unsigned* Pr1 = Pr0 + 36;
                Pr0[g] = f2tf(p00);      Pr0[8 + g] = f2tf(p02);
                Pr0[16 + g] = f2tf(p10); Pr0[24 + g] = f2tf(p12);
                Pr1[g] = f2tf(p01);      Pr1[8 + g] = f2tf(p03);
                Pr1[16 + g] = f2tf(p11); Pr1[24 + g] = f2tf(p13);
            }
            __syncwarp();

            // O^T[d 128][q 8] += V^T P^T
#pragma unroll
            for (int ks = 0; ks < 4; ks++) {
                const unsigned* pb = Ps + (w * 8 + g) * 36 + ks * 8 + t;
                const unsigned b0 = pb[0], b1 = pb[4];
#pragma unroll
                for (int mt = 0; mt < 8; mt++) {
                    const unsigned* ap = Vc + (mt * 16 + g) * 36 + ks * 8 + t;
                    unsigned a[4] = {ap[0], ap[8 * 36], ap[4], ap[8 * 36 + 4]};
                    mma8(o[mt], a, b0, b1);
                }
            }
            __syncwarp();
        }

        // epilogue: thread owns q rows (q0+w*8+2t, +1), d cols mt*16+g, +8
        const float i0 = 1.f / l0, i1 = 1.f / l1;
        float* r0p = Out + (size_t)(q0 + w * 8 + 2 * t) * D_MODEL + h * HDIM;
        float* r1p = r0p + D_MODEL;
#pragma unroll
        for (int mt = 0; mt < 8; mt++) {
            const int d0 = mt * 16 + g, d1 = d0 + 8;
            float v00 = o[mt][0] * i0, v10 = o[mt][1] * i1;
            float v01 = o[mt][2] * i0, v11 = o[mt][3] * i1;
            if (ph == 1) {
                v00 += r0p[d0]; v10 += r1p[d0];
                v01 += r0p[d1]; v11 += r1p[d1];
            }
            r0p[d0] = v00; r1p[d0] = v10;
            r0p[d1] = v01; r1p[d1] = v11;
        }
    }
}

// ---------------- host launcher ----------------
extern "C" void kernel_launch(void* const* d_in, const int* in_sizes, int n_in,
                              void* d_out, int out_size)
{
    (void)in_sizes; (void)n_in; (void)out_size;
    const float* x    = (const float*)d_in[0];
    const float* img  = (const float*)d_in[1];
    const float* cosr = (const float*)d_in[2];
    const float* sinr = (const float*)d_in[3];
    const float* Wq   = (const float*)d_in[4];
    const float* bq   = (const float*)d_in[5];
    const float* Wk   = (const float*)d_in[6];
    const float* bk   = (const float*)d_in[7];
    const float* Wv   = (const float*)d_in[8];
    const float* bv   = (const float*)d_in[9];
    const float* qd   = (const float*)d_in[10];
    const float* qu   = (const float*)d_in[11];
    const float* kd   = (const float*)d_in[12];
    const float* ku   = (const float*)d_in[13];
    const float* vd   = (const float*)d_in[14];
    const float* vu   = (const float*)d_in[15];
    const float* nqw  = (const float*)d_in[16];
    const float* nkw  = (const float*)d_in[17];
    const float* Wkip = (const float*)d_in[18];
    const float* Wvip = (const float*)d_in[19];
    float* out = (float*)d_out;

    float *q, *k, *vt, *kip, *vipt, *lt, *xr, *imgr;
    cudaGetSymbolAddress((void**)&q,    g_q);
    cudaGetSymbolAddress((void**)&k,    g_k);
    cudaGetSymbolAddress((void**)&vt,   g_vt);
    cudaGetSymbolAddress((void**)&kip,  g_kip);
    cudaGetSymbolAddress((void**)&vipt, g_vipt);
    cudaGetSymbolAddress((void**)&lt,   g_lt);
    cudaGetSymbolAddress((void**)&xr,   g_xr);
    cudaGetSymbolAddress((void**)&imgr, g_imgr);

    const int GSM = 6 * 2560 * 4;
    cudaFuncSetAttribute(gemm_tc<false>, cudaFuncAttributeMaxDynamicSharedMemorySize, GSM);
    cudaFuncSetAttribute(gemm_tc<true>,  cudaFuncAttributeMaxDynamicSharedMemorySize, GSM);

    // 1) RNA tf32 rounding pre-pass: A-side only (x, img)
    {
        R2 R;
        R.s[0] = x;   R.d[0] = xr;   R.n[0] = S_TOK * D_MODEL;
        R.s[1] = img; R.d[1] = imgr; R.n[1] = T_IPN * D_IPN;
        round_tf32_kernel<<<dim3(512, 2), 256>>>(R);
    }
    const float* xcr = xr + (size_t)BLOCK_TOK * D_MODEL;

    // 2) mega GEMM: z0-2 QKV (V transposed out), z3-5 LoRA-down, z6-7 IP proj
    {
        GemmB P;
        for (int i = 0; i < 8; i++) { P.tr[i] = 0; P.ldt[i] = 1; P.stoff[i] = 0; P.tokoff[i] = 0; P.w[i] = nullptr; }
        P.A[0] = xr; P.A[1] = xr; P.A[2] = xr;
        P.Bm[0] = Wq; P.Bm[1] = Wk; P.Bm[2] = Wv;
        P.bias[0] = bq; P.bias[1] = bk; P.bias[2] = bv;
        P.C[0] = q;  P.C[1] = k;  P.C[2] = vt;
        P.w[0] = nqw; P.w[1] = nkw;
        P.M[0] = P.M[1] = P.M[2] = S_TOK;
        P.N[0] = P.N[1] = P.N[2] = D_MODEL;
        P.K[0] = P.K[1] = P.K[2] = D_MODEL;
        P.nrm[0] = 4; P.nrm[1] = 3; P.nrm[2] = 1;
        P.rowlim[0] = P.rowlim[1] = P.rowlim[2] = BLOCK_TOK;
        P.tr[2] = 1; P.ldt[2] = S_TOK; P.stoff[2] = 0;
        P.A[3] = xcr; P.A[4] = xcr; P.A[5] = xcr;
        P.Bm[3] = qd; P.Bm[4] = kd; P.Bm[5] = vd;
        P.bias[3] = P.bias[4] = P.bias[5] = nullptr;
        P.C[3] = lt; P.C[4] = lt + CONDN * RANKN; P.C[5] = lt + 2 * CONDN * RANKN;
        P.M[3] = P.M[4] = P.M[5] = CONDN;
        P.N[3] = P.N[4] = P.N[5] = RANKN;
        P.K[3] = P.K[4] = P.K[5] = D_MODEL;
        P.nrm[3] = P.nrm[4] = P.nrm[5] = 1;
        P.rowlim[3] = P.rowlim[4] = P.rowlim[5] = BIGROW;
        P.A[6] = imgr; P.A[7] = imgr;
        P.Bm[6] = Wkip; P.Bm[7] = Wvip;
        P.bias[6] = P.bias[7] = nullptr;
        P.C[6] = kip; P.C[7] = vipt;
        P.M[6] = P.M[7] = T_IPN;
        P.N[6] = P.N[7] = D_MODEL;
        P.K[6] = P.K[7] = D_IPN;
        P.nrm[6] = 2; P.nrm[7] = 1;
        P.rowlim[6] = P.rowlim[7] = BIGROW;
        P.tr[7] = 1; P.ldt[7] = T_IPN; P.stoff[7] = 0;
        gemm_tc<false><<<dim3(D_MODEL / 128, S_TOK / 128, 8), 256, GSM>>>(P, cosr, sinr);
    }
    // 3) LoRA up: accumulate into q/k/vt cond rows, fused norm+rope+round
    {
        GemmB P;
        for (int i = 0; i < 8; i++) {
            P.A[i] = nullptr; P.Bm[i] = nullptr; P.bias[i] = nullptr; P.C[i] = nullptr;
            P.w[i] = nullptr; P.M[i] = 0; P.N[i] = 0; P.K[i] = 16;
            P.nrm[i] = 0; P.rowlim[i] = BIGROW; P.tokoff[i] = 0;
            P.tr[i] = 0; P.ldt[i] = 1; P.stoff[i] = 0;
        }
        P.A[0] = lt; P.A[1] = lt + CONDN * RANKN; P.A[2] = lt + 2 * CONDN * RANKN;
        P.Bm[0] = qu; P.Bm[1] = ku; P.Bm[2] = vu;
        P.C[0] = q + (size_t)BLOCK_TOK * D_MODEL;
        P.C[1] = k + (size_t)BLOCK_TOK * D_MODEL;
        P.C[2] = vt;
        P.w[0] = nqw; P.w[1] = nkw;
        for (int i = 0; i < 3; i++) {
            P.M[i] = CONDN; P.N[i] = D_MODEL; P.K[i] = RANKN;
            P.tokoff[i] = BLOCK_TOK;
        }
        P.nrm[0] = 4; P.nrm[1] = 3; P.nrm[2] = 1;
        P.tr[2] = 1; P.ldt[2] = S_TOK; P.stoff[2] = BLOCK_TOK;
        gemm_tc<true><<<dim3(D_MODEL / 128, CONDN / 128, 3), 256, GSM>>>(P, cosr, sinr);
    }
    // 4) fused attention: main (masked) + IP phase, S^T/O^T form
    {
        const int ASM = (2 * KST + 2 * VST + 64 * 36) * 4;   // 79872 B
        cudaFuncSetAttribute(attn_tc, cudaFuncAttributeMaxDynamicSharedMemorySize, ASM);
        attn_tc<<<dim3(S_TOK / 64, NHEAD), 256, ASM>>>(
            (const unsigned*)q, (const unsigned*)k, (const unsigned*)vt,
            (const unsigned*)kip, (const unsigned*)vipt, out);
    }
}

// round 10
// speedup vs baseline: 1.1934x; 1.1934x over previous
#include <cuda_runtime.h>

#define S_TOK     2304
#define D_MODEL   3072
#define NHEAD     24
#define HDIM      128
#define BLOCK_TOK 2048
#define CONDN     256
#define RANKN     128
#define T_IPN     128
#define D_IPN     4096
#define EPSV      1e-5f
// (1/sqrt(128)) * log2(e): softmax computed in exp2 domain
#define QSCALE    0.1275173e+0f
#define BIGROW    0x7fffffff

// ---------------- device scratch ----------------
__device__ float g_q[S_TOK * D_MODEL];
__device__ float g_k[S_TOK * D_MODEL];
__device__ float g_vt[D_MODEL * S_TOK];     // V transposed: [d 3072][tok 2304]
__device__ float g_kip[T_IPN * D_MODEL];
__device__ float g_vipt[D_MODEL * T_IPN];   // V_ip transposed
__device__ float g_lt[3 * CONDN * RANKN];
__device__ float g_xr[S_TOK * D_MODEL];     // RNA-tf32-rounded A-side operands
__device__ float g_imgr[T_IPN * D_IPN];

// ---------------- helpers ----------------
__device__ __forceinline__ unsigned f2tf(float f) {
    unsigned u;
    asm("cvt.rna.tf32.f32 %0, %1;" : "=r"(u) : "f"(f));
    return u;
}
__device__ __forceinline__ void mma8(float* c, const unsigned* a, unsigned b0, unsigned b1) {
    asm volatile(
        "mma.sync.aligned.m16n8k8.row.col.f32.tf32.tf32.f32 "
        "{%0,%1,%2,%3}, {%4,%5,%6,%7}, {%8,%9}, {%0,%1,%2,%3};"
        : "+f"(c[0]), "+f"(c[1]), "+f"(c[2]), "+f"(c[3])
        : "r"(a[0]), "r"(a[1]), "r"(a[2]), "r"(a[3]), "r"(b0), "r"(b1));
}
__device__ __forceinline__ void ldsm4(unsigned* r, unsigned addr) {
    asm volatile("ldmatrix.sync.aligned.m8n8.x4.shared.b16 {%0,%1,%2,%3}, [%4];"
        : "=r"(r[0]), "=r"(r[1]), "=r"(r[2]), "=r"(r[3]) : "r"(addr));
}
__device__ __forceinline__ void cpa16(unsigned dst, const void* src) {
    asm volatile("cp.async.cg.shared.global [%0], [%1], 16;" :: "r"(dst), "l"(src));
}
__device__ __forceinline__ void cp_commit() { asm volatile("cp.async.commit_group;"); }
__device__ __forceinline__ void cp_wait0() { asm volatile("cp.async.wait_group 0;"); }
__device__ __forceinline__ void cp_wait1() { asm volatile("cp.async.wait_group 1;"); }

// ---------------- RNA tf32 rounding pre-pass (A-side only) ----------------
struct R2 { const float* s[2]; float* d[2]; int n[2]; };
__global__ void round_tf32_kernel(R2 P) {
    const int y = blockIdx.y;
    const float4* src = (const float4*)P.s[y];
    float4* dst = (float4*)P.d[y];
    const int n4 = P.n[y] >> 2;
    for (int i = blockIdx.x * blockDim.x + threadIdx.x; i < n4; i += gridDim.x * blockDim.x) {
        float4 v = src[i];
        v.x = __uint_as_float(f2tf(v.x));
        v.y = __uint_as_float(f2tf(v.y));
        v.z = __uint_as_float(f2tf(v.z));
        v.w = __uint_as_float(f2tf(v.w));
        dst[i] = v;
    }
}

// ============ batched GEMM (A pre-rounded, B cvt-in-loop, fused norm epilogue) ============
struct GemmB {
    const float* A[8]; const float* Bm[8]; const float* bias[8]; float* C[8];
    const float* w[8];
    int M[8], N[8], K[8], nrm[8], rowlim[8], tokoff[8], tr[8], ldt[8], stoff[8];
};

template <bool ACC>
__global__ __launch_bounds__(256, 2) void gemm_tc(GemmB P, const float* cs, const float* sn)
{
    extern __shared__ unsigned smg[];
    unsigned* As = smg;
    unsigned* Bs = smg + 3 * 2560;

    const int z = blockIdx.z;
    const int M = P.M[z], N = P.N[z], K = P.K[z];
    const int bm = blockIdx.y << 7, bn = blockIdx.x << 7;
    if (bm >= M || bn >= N) return;
    const float* A = P.A[z];
    const float* Bw = P.Bm[z];
    const float* bias = P.bias[z];
    float* C = P.C[z];
    const float* wp = P.w[z];
    const int mode = (bm >= P.rowlim[z]) ? 0 : P.nrm[z];
    const int tokoff = P.tokoff[z];
    const int tr = P.tr[z], ldt = P.ldt[z], stoff = P.stoff[z];

    const int tid = threadIdx.x;
    const int lw = tid & 31, w = tid >> 5, g = lw >> 2, t = lw & 3;
    const int wm = w & 1, wn = w >> 1;

    const int lrow = tid >> 1, lseg = (tid & 1) * 8;
    const float* Arow = A + (size_t)(bm + lrow) * K + lseg;
    const float* Brow = Bw + (size_t)(bn + lrow) * K + lseg;
    const unsigned as_u = (unsigned)__cvta_generic_to_shared(As) + (lrow * 20 + lseg) * 4;
    const unsigned bs_u = (unsigned)__cvta_generic_to_shared(Bs) + (lrow * 20 + lseg) * 4;

    float acc[4][4][4];
#pragma unroll
    for (int mt = 0; mt < 4; mt++)
#pragma unroll
        for (int nt = 0; nt < 4; nt++)
#pragma unroll
            for (int i = 0; i < 4; i++) acc[mt][nt][i] = 0.f;

    const int niter = K >> 4;
    cpa16(as_u, Arow);              cpa16(as_u + 16, Arow + 4);
    cpa16(bs_u, Brow);              cpa16(bs_u + 16, Brow + 4);
    cp_commit();
    {
        const unsigned off = 2560u * 4u;
        cpa16(as_u + off, Arow + 16);   cpa16(as_u + off + 16, Arow + 20);
        cpa16(bs_u + off, Brow + 16);   cpa16(bs_u + off + 16, Brow + 20);
        cp_commit();
    }

    int st = 0, ld = 2;
    for (int it = 0; it < niter; it++) {
        if (it + 1 < niter) cp_wait1(); else cp_wait0();
        __syncthreads();
        if (it + 2 < niter) {
            const int k0 = (it + 2) << 4;
            const unsigned off = (unsigned)(ld * 2560 * 4);
            cpa16(as_u + off, Arow + k0);   cpa16(as_u + off + 16, Arow + k0 + 4);
            cpa16(bs_u + off, Brow + k0);   cpa16(bs_u + off + 16, Brow + k0 + 4);
            cp_commit();
            ld = (ld == 2) ? 0 : ld + 1;
        }
        const unsigned* Ac = As + st * 2560;
        const unsigned* Bc = Bs + st * 2560;
        st = (st == 2) ? 0 : st + 1;
#pragma unroll
        for (int ks = 0; ks < 2; ks++) {
            const int kr = ks * 8 + t;
            unsigned af[4][4], bf[4][2];
#pragma unroll
            for (int mt = 0; mt < 4; mt++) {
                const unsigned* ap = Ac + (wm * 64 + mt * 16 + g) * 20 + kr;
                af[mt][0] = ap[0];
                af[mt][1] = ap[160];
                af[mt][2] = ap[4];
                af[mt][3] = ap[164];
            }
#pragma unroll
            for (int nt = 0; nt < 4; nt++) {
                const float* bp = (const float*)(Bc + (wn * 32 + nt * 8 + g) * 20 + kr);
                bf[nt][0] = f2tf(bp[0]);
                bf[nt][1] = f2tf(bp[4]);
            }
#pragma unroll
            for (int mt = 0; mt < 4; mt++)
#pragma unroll
                for (int nt = 0; nt < 4; nt++)
                    mma8(acc[mt][nt], af[mt], bf[nt][0], bf[nt][1]);
        }
    }

#pragma unroll
    for (int mt = 0; mt < 4; mt++) {
        const int r0 = bm + wm * 64 + mt * 16 + g;
        const int r1 = r0 + 8;
#pragma unroll
        for (int nt = 0; nt < 4; nt++) {
            const int cc = bn + wn * 32 + nt * 8 + 2 * t;
            if (bias) {
                float bx = bias[cc], by = bias[cc + 1];
                acc[mt][nt][0] += bx; acc[mt][nt][1] += by;
                acc[mt][nt][2] += bx; acc[mt][nt][3] += by;
            }
            if (ACC) {
                if (tr) {
                    acc[mt][nt][0] += C[(size_t)cc * ldt + stoff + r0];
                    acc[mt][nt][1] += C[(size_t)(cc + 1) * ldt + stoff + r0];
                    acc[mt][nt][2] += C[(size_t)cc * ldt + stoff + r1];
                    acc[mt][nt][3] += C[(size_t)(cc + 1) * ldt + stoff + r1];
                } else {
                    float2 e0 = *(const float2*)(C + (size_t)r0 * N + cc);
                    float2 e1 = *(const float2*)(C + (size_t)r1 * N + cc);
                    acc[mt][nt][0] += e0.x; acc[mt][nt][1] += e0.y;
                    acc[mt][nt][2] += e1.x; acc[mt][nt][3] += e1.y;
                }
            }
        }
    }

    float inv0[4], inv1[4];
    if (mode >= 2) {
        __syncthreads();
        float* ssb = (float*)smg;
#pragma unroll
        for (int mt = 0; mt < 4; mt++) {
            float s0 = 0.f, s1 = 0.f;
#pragma unroll
            for (int nt = 0; nt < 4; nt++) {
                s0 += acc[mt][nt][0] * acc[mt][nt][0] + acc[mt][nt][1] * acc[mt][nt][1];
                s1 += acc[mt][nt][2] * acc[mt][nt][2] + acc[mt][nt][3] * acc[mt][nt][3];
            }
            s0 += __shfl_xor_sync(0xffffffffu, s0, 1);
            s0 += __shfl_xor_sync(0xffffffffu, s0, 2);
            s1 += __shfl_xor_sync(0xffffffffu, s1, 1);
            s1 += __shfl_xor_sync(0xffffffffu, s1, 2);
            if (t == 0) {
                const int rr = wm * 64 + mt * 16 + g;
                ssb[rr * 4 + wn] = s0;
                ssb[(rr + 8) * 4 + wn] = s1;
            }
        }
        __syncthreads();
#pragma unroll
        for (int mt = 0; mt < 4; mt++) {
            const int rr = wm * 64 + mt * 16 + g;
            float4 a = ((const float4*)ssb)[rr];
            float4 b = ((const float4*)ssb)[rr + 8];
            inv0[mt] = rsqrtf((a.x + a.y + a.z + a.w) * (1.0f / HDIM) + EPSV);
            inv1[mt] = rsqrtf((b.x + b.y + b.z + b.w) * (1.0f / HDIM) + EPSV);
        }
    }

#pragma unroll
    for (int mt = 0; mt < 4; mt++) {
        const int r0 = bm + wm * 64 + mt * 16 + g;
        const int r1 = r0 + 8;
#pragma unroll
        for (int nt = 0; nt < 4; nt++) {
            const int d = wn * 32 + nt * 8 + 2 * t;
            const int cc = bn + d;
            float2 v0 = make_float2(acc[mt][nt][0], acc[mt][nt][1]);
            float2 v1 = make_float2(acc[mt][nt][2], acc[mt][nt][3]);
            if (mode >= 2) {
                v0.x *= inv0[mt]; v0.y *= inv0[mt];
                v1.x *= inv1[mt]; v1.y *= inv1[mt];
                if (wp) {
                    float2 ww = *(const float2*)(wp + d);
                    v0.x *= ww.x; v0.y *= ww.y;
                    v1.x *= ww.x; v1.y *= ww.y;
                }
            }
            if (mode >= 3) {
                const size_t t0 = (size_t)(tokoff + r0) * HDIM + d;
                const size_t t1 = (size_t)(tokoff + r1) * HDIM + d;
                float2 c0 = *(const float2*)(cs + t0);
                float2 s0v = *(const float2*)(sn + t0);
                float2 c1 = *(const float2*)(cs + t1);
                float2 s1v = *(const float2*)(sn + t1);
                float e0 = v0.x * c0.x - v0.y * s0v.x;
                float o0 = v0.y * c0.y + v0.x * s0v.y;
                float e1 = v1.x * c1.x - v1.y * s1v.x;
                float o1 = v1.y * c1.y + v1.x * s1v.y;
                v0.x = e0; v0.y = o0; v1.x = e1; v1.y = o1;
            }
            if (mode == 4) {
                v0.x *= QSCALE; v0.y *= QSCALE;
                v1.x *= QSCALE; v1.y *= QSCALE;
            }
            if (mode >= 1) {
                v0.x = __uint_as_float(f2tf(v0.x));
                v0.y = __uint_as_float(f2tf(v0.y));
                v1.x = __uint_as_float(f2tf(v1.x));
                v1.y = __uint_as_float(f2tf(v1.y));
            }
            if (tr) {
                C[(size_t)cc * ldt + stoff + r0] = v0.x;
                C[(size_t)(cc + 1) * ldt + stoff + r0] = v0.y;
                C[(size_t)cc * ldt + stoff + r1] = v1.x;
                C[(size_t)(cc + 1) * ldt + stoff + r1] = v1.y;
            } else {
                *(float2*)(C + (size_t)r0 * N + cc) = v0;
                *(float2*)(C + (size_t)r1 * N + cc) = v1;
            }
        }
    }
}

// ============ flash attention: R4 shape + ldmatrix operand loads ============
// Bq=128 (8 warps x 16 q), Bk=64. K smem [kv 64][132]; V smem transposed [d 128][68]
// (fed from pre-transposed g_vt); P smem [q 128][68]. All mma operands via LDSM.x4.
#define KSTW 8448   // 64*132
#define VSTW 8704   // 128*68
__global__ __launch_bounds__(256, 1) void attn_tc(
    const unsigned* __restrict__ Q, const unsigned* __restrict__ Km,
    const unsigned* __restrict__ Vtm, const unsigned* __restrict__ Ki,
    const unsigned* __restrict__ Vti, float* __restrict__ Out)
{
    extern __shared__ unsigned smu[];
    unsigned* Ks = smu;                        // [2][64][132]
    unsigned* Vs = smu + 2 * KSTW;             // [2][128][68]
    unsigned* Ps = smu + 2 * KSTW + 2 * VSTW;  // [128][68]

    const int tid = threadIdx.x;
    const int l = tid & 31, w = tid >> 5;
    const int g = l >> 2, t = l & 3;
    const int h = blockIdx.y;
    const int q0 = blockIdx.x << 7;
    const int qr = q0 + w * 16 + g;

    unsigned qf[16][4];
    {
        const unsigned* qp = Q + (size_t)qr * D_MODEL + h * HDIM;
        const unsigned* qp8 = qp + (size_t)8 * D_MODEL;
#pragma unroll
        for (int ks = 0; ks < 16; ks++) {
            const int cb = ks * 8 + t;
            qf[ks][0] = qp[cb];
            qf[ks][1] = qp8[cb];
            qf[ks][2] = qp[cb + 4];
            qf[ks][3] = qp8[cb + 4];
        }
    }

    // tile-fill mappings
    const int krow = tid >> 2, kseg = (tid & 3) * 32;
    const int vrow = tid >> 1, vseg = (tid & 1) * 32;
    const unsigned ks_u = (unsigned)__cvta_generic_to_shared(Ks) + (krow * 132 + kseg) * 4;
    const unsigned vs_u = (unsigned)__cvta_generic_to_shared(Vs) + (vrow * 68 + vseg) * 4;

    // ldmatrix per-thread address parts
    const int lr = l & 7, lh = (l >> 3) & 1, lq = l >> 4;
    const unsigned kmat_u = (unsigned)__cvta_generic_to_shared(Ks) + ((lq * 8 + lr) * 132 + lh * 4) * 4;
    const unsigned vmat_u = (unsigned)__cvta_generic_to_shared(Vs) + ((lq * 8 + lr) * 68 + lh * 4) * 4;
    const unsigned pmat_u = (unsigned)__cvta_generic_to_shared(Ps) + ((w * 16 + lh * 8 + lr) * 68 + lq * 4) * 4;
    unsigned* Prow0 = Ps + (w * 16 + g) * 68 + 2 * t;
    unsigned* Prow1 = Prow0 + 8 * 68;

    float* op0 = Out + (size_t)qr * D_MODEL + h * HDIM;
    float* op1 = op0 + (size_t)8 * D_MODEL;

#pragma unroll 1
    for (int ph = 0; ph < 2; ph++) {
        const unsigned* Kb = ph ? Ki : Km;
        const unsigned* Vb = ph ? Vti : Vtm;
        const int toks = ph ? T_IPN : S_TOK;
        const int kt0 = (ph == 0 && q0 >= BLOCK_TOK) ? BLOCK_TOK : 0;
        const int ntiles = (toks - kt0) >> 6;

        float o[16][4];
#pragma unroll
        for (int nt = 0; nt < 16; nt++)
#pragma unroll
            for (int i = 0; i < 4; i++) o[nt][i] = 0.f;
        float mrow0 = -1e30f, mrow1 = -1e30f, lrow0 = 0.f, lrow1 = 0.f;

        __syncthreads();
        {
            const unsigned* kg = Kb + (size_t)(kt0 + krow) * D_MODEL + h * HDIM + kseg;
            const unsigned* vg = Vb + (size_t)(h * HDIM + vrow) * toks + kt0 + vseg;
#pragma unroll
            for (int c = 0; c < 8; c++) {
                cpa16(ks_u + c * 16, kg + c * 4);
                cpa16(vs_u + c * 16, vg + c * 4);
            }
            cp_commit();
        }

        for (int it = 0; it < ntiles; it++) {
            const int cur = it & 1;
            cp_wait0();
            __syncthreads();
            if (it + 1 < ntiles) {
                const int kt = kt0 + (it + 1) * 64;
                const unsigned* kg = Kb + (size_t)(kt + krow) * D_MODEL + h * HDIM + kseg;
                const unsigned* vg = Vb + (size_t)(h * HDIM + vrow) * toks + kt + vseg;
                const unsigned ko = ks_u + (cur ^ 1) * KSTW * 4;
                const unsigned vo = vs_u + (cur ^ 1) * VSTW * 4;
#pragma unroll
                for (int c = 0; c < 8; c++) {
                    cpa16(ko + c * 16, kg + c * 4);
                    cpa16(vo + c * 16, vg + c * 4);
                }
                cp_commit();
            }
            const unsigned Kc_u = kmat_u + cur * KSTW * 4;
            const unsigned Vc_u = vmat_u + cur * VSTW * 4;

            // S = Q K^T  (B-frags of K via LDSM.x4: tile pair = 16 kv rows)
            float s[8][4];
#pragma unroll
            for (int nt = 0; nt < 8; nt++)
#pragma unroll
                for (int i = 0; i < 4; i++) s[nt][i] = 0.f;
#pragma unroll
            for (int ks = 0; ks < 16; ks++) {
#pragma unroll
                for (int ntp = 0; ntp < 4; ntp++) {
                    unsigned b[4];
                    ldsm4(b, Kc_u + (unsigned)((ntp * 16 * 132 + ks * 8) * 4));
                    mma8(s[ntp * 2],     qf[ks], b[0], b[1]);
                    mma8(s[ntp * 2 + 1], qf[ks], b[2], b[3]);
                }
            }

            // online softmax (rows r0 = w*16+g, r1 = r0+8)
            float mx0 = -1e30f, mx1 = -1e30f;
#pragma unroll
            for (int nt = 0; nt < 8; nt++) {
                mx0 = fmaxf(mx0, fmaxf(s[nt][0], s[nt][1]));
                mx1 = fmaxf(mx1, fmaxf(s[nt][2], s[nt][3]));
            }
            mx0 = fmaxf(mx0, __shfl_xor_sync(0xffffffffu, mx0, 1));
            mx0 = fmaxf(mx0, __shfl_xor_sync(0xffffffffu, mx0, 2));
            mx1 = fmaxf(mx1, __shfl_xor_sync(0xffffffffu, mx1, 1));
            mx1 = fmaxf(mx1, __shfl_xor_sync(0xffffffffu, mx1, 2));
            const float mn0 = fmaxf(mrow0, mx0), mn1 = fmaxf(mrow1, mx1);
            const float al0 = exp2f(mrow0 - mn0), al1 = exp2f(mrow1 - mn1);
            mrow0 = mn0; mrow1 = mn1;

            float sum0 = 0.f, sum1 = 0.f;
#pragma unroll
            for (int nt = 0; nt < 8; nt++) {
                float p0 = exp2f(s[nt][0] - mn0);
                float p1 = exp2f(s[nt][1] - mn0);
                float p2 = exp2f(s[nt][2] - mn1);
                float p3 = exp2f(s[nt][3] - mn1);
                sum0 += p0 + p1;
                sum1 += p2 + p3;
                *(uint2*)(Prow0 + nt * 8) = make_uint2(f2tf(p0), f2tf(p1));
                *(uint2*)(Prow1 + nt * 8) = make_uint2(f2tf(p2), f2tf(p3));
            }
            sum0 += __shfl_xor_sync(0xffffffffu, sum0, 1);
            sum0 += __shfl_xor_sync(0xffffffffu, sum0, 2);
            sum1 += __shfl_xor_sync(0xffffffffu, sum1, 1);
            sum1 += __shfl_xor_sync(0xffffffffu, sum1, 2);
            lrow0 = lrow0 * al0 + sum0;
            lrow1 = lrow1 * al1 + sum1;
#pragma unroll
            for (int nt = 0; nt < 16; nt++) {
                o[nt][0] *= al0; o[nt][1] *= al0;
                o[nt][2] *= al1; o[nt][3] *= al1;
            }
            __syncwarp();

            // O += P V  (A = P rows of this warp, B = V^T tiles, all LDSM.x4)
#pragma unroll
            for (int ks = 0; ks < 8; ks++) {
                unsigned pa[4];
                ldsm4(pa, pmat_u + (unsigned)(ks * 8 * 4));
#pragma unroll
                for (int ntp = 0; ntp < 8; ntp++) {
                    unsigned b[4];
                    ldsm4(b, Vc_u + (unsigned)((ntp * 16 * 68 + ks * 8) * 4));
                    mma8(o[ntp * 2],     pa, b[0], b[1]);
                    mma8(o[ntp * 2 + 1], pa, b[2], b[3]);
                }
            }
            __syncwarp();
        }

        const float inv0 = 1.f / lrow0, inv1 = 1.f / lrow1;
#pragma unroll
        for (int nt = 0; nt < 16; nt++) {
            const int cc = nt * 8 + 2 * t;
            float2 v0 = make_float2(o[nt][0] * inv0, o[nt][1] * inv0);
            float2 v1 = make_float2(o[nt][2] * inv1, o[nt][3] * inv1);
            if (ph == 1) {
                float2 e0 = *(const float2*)(op0 + cc);
                float2 e1 = *(const float2*)(op1 + cc);
                v0.x += e0.x; v0.y += e0.y; v1.x += e1.x; v1.y += e1.y;
            }
            *(float2*)(op0 + cc) = v0;
            *(float2*)(op1 + cc) = v1;
        }
    }
}

// ---------------- host launcher ----------------
extern "C" void kernel_launch(void* const* d_in, const int* in_sizes, int n_in,
                              void* d_out, int out_size)
{
    (void)in_sizes; (void)n_in; (void)out_size;
    const float* x    = (const float*)d_in[0];
    const float* img  = (const float*)d_in[1];
    const float* cosr = (const float*)d_in[2];
    const float* sinr = (const float*)d_in[3];
    const float* Wq   = (const float*)d_in[4];
    const float* bq   = (const float*)d_in[5];
    const float* Wk   = (const float*)d_in[6];
    const float* bk   = (const float*)d_in[7];
    const float* Wv   = (const float*)d_in[8];
    const float* bv   = (const float*)d_in[9];
    const float* qd   = (const float*)d_in[10];
    const float* qu   = (const float*)d_in[11];
    const float* kd   = (const float*)d_in[12];
    const float* ku   = (const float*)d_in[13];
    const float* vd   = (const float*)d_in[14];
    const float* vu   = (const float*)d_in[15];
    const float* nqw  = (const float*)d_in[16];
    const float* nkw  = (const float*)d_in[17];
    const float* Wkip = (const float*)d_in[18];
    const float* Wvip = (const float*)d_in[19];
    float* out = (float*)d_out;

    float *q, *k, *vt, *kip, *vipt, *lt, *xr, *imgr;
    cudaGetSymbolAddress((void**)&q,    g_q);
    cudaGetSymbolAddress((void**)&k,    g_k);
    cudaGetSymbolAddress((void**)&vt,   g_vt);
    cudaGetSymbolAddress((void**)&kip,  g_kip);
    cudaGetSymbolAddress((void**)&vipt, g_vipt);
    cudaGetSymbolAddress((void**)&lt,   g_lt);
    cudaGetSymbolAddress((void**)&xr,   g_xr);
    cudaGetSymbolAddress((void**)&imgr, g_imgr);

    const int GSM = 6 * 2560 * 4;
    cudaFuncSetAttribute(gemm_tc<false>, cudaFuncAttributeMaxDynamicSharedMemorySize, GSM);
    cudaFuncSetAttribute(gemm_tc<true>,  cudaFuncAttributeMaxDynamicSharedMemorySize, GSM);

    // 1) RNA tf32 rounding pre-pass: A-side only (x, img)
    {
        R2 R;
        R.s[0] = x;   R.d[0] = xr;   R.n[0] = S_TOK * D_MODEL;
        R.s[1] = img; R.d[1] = imgr; R.n[1] = T_IPN * D_IPN;
        round_tf32_kernel<<<dim3(512, 2), 256>>>(R);
    }
    const float* xcr = xr + (size_t)BLOCK_TOK * D_MODEL;

    // 2) mega GEMM: z0-2 QKV (V transposed out), z3-5 LoRA-down, z6-7 IP proj
    {
        GemmB P;
        for (int i = 0; i < 8; i++) { P.tr[i] = 0; P.ldt[i] = 1; P.stoff[i] = 0; P.tokoff[i] = 0; P.w[i] = nullptr; }
        P.A[0] = xr; P.A[1] = xr; P.A[2] = xr;
        P.Bm[0] = Wq; P.Bm[1] = Wk; P.Bm[2] = Wv;
        P.bias[0] = bq; P.bias[1] = bk; P.bias[2] = bv;
        P.C[0] = q;  P.C[1] = k;  P.C[2] = vt;
        P.w[0] = nqw; P.w[1] = nkw;
        P.M[0] = P.M[1] = P.M[2] = S_TOK;
        P.N[0] = P.N[1] = P.N[2] = D_MODEL;
        P.K[0] = P.K[1] = P.K[2] = D_MODEL;
        P.nrm[0] = 4; P.nrm[1] = 3; P.nrm[2] = 1;
        P.rowlim[0] = P.rowlim[1] = P.rowlim[2] = BLOCK_TOK;
        P.tr[2] = 1; P.ldt[2] = S_TOK; P.stoff[2] = 0;
        P.A[3] = xcr; P.A[4] = xcr; P.A[5] = xcr;
        P.Bm[3] = qd; P.Bm[4] = kd; P.Bm[5] = vd;
        P.bias[3] = P.bias[4] = P.bias[5] = nullptr;
        P.C[3] = lt; P.C[4] = lt + CONDN * RANKN; P.C[5] = lt + 2 * CONDN * RANKN;
        P.M[3] = P.M[4] = P.M[5] = CONDN;
        P.N[3] = P.N[4] = P.N[5] = RANKN;
        P.K[3] = P.K[4] = P.K[5] = D_MODEL;
        P.nrm[3] = P.nrm[4] = P.nrm[5] = 1;
        P.rowlim[3] = P.rowlim[4] = P.rowlim[5] = BIGROW;
        P.A[6] = imgr; P.A[7] = imgr;
        P.Bm[6] = Wkip; P.Bm[7] = Wvip;
        P.bias[6] = P.bias[7] = nullptr;
        P.C[6] = kip; P.C[7] = vipt;
        P.M[6] = P.M[7] = T_IPN;
        P.N[6] = P.N[7] = D_MODEL;
        P.K[6] = P.K[7] = D_IPN;
        P.nrm[6] = 2; P.nrm[7] = 1;
        P.rowlim[6] = P.rowlim[7] = BIGROW;
        P.tr[7] = 1; P.ldt[7] = T_IPN; P.stoff[7] = 0;
        gemm_tc<false><<<dim3(D_MODEL / 128, S_TOK / 128, 8), 256, GSM>>>(P, cosr, sinr);
    }
    // 3) LoRA up: accumulate into q/k/vt cond rows, fused norm+rope+round
    {
        GemmB P;
        for (int i = 0; i < 8; i++) {
            P.A[i] = nullptr; P.Bm[i] = nullptr; P.bias[i] = nullptr; P.C[i] = nullptr;
            P.w[i] = nullptr; P.M[i] = 0; P.N[i] = 0; P.K[i] = 16;
            P.nrm[i] = 0; P.rowlim[i] = BIGROW; P.tokoff[i] = 0;
            P.tr[i] = 0; P.ldt[i] = 1; P.stoff[i] = 0;
        }
        P.A[0] = lt; P.A[1] = lt + CONDN * RANKN; P.A[2] = lt + 2 * CONDN * RANKN;
        P.Bm[0] = qu; P.Bm[1] = ku; P.Bm[2] = vu;
        P.C[0] = q + (size_t)BLOCK_TOK * D_MODEL;
        P.C[1] = k + (size_t)BLOCK_TOK * D_MODEL;
        P.C[2] = vt;
        P.w[0] = nqw; P.w[1] = nkw;
        for (int i = 0; i < 3; i++) {
            P.M[i] = CONDN; P.N[i] = D_MODEL; P.K[i] = RANKN;
            P.tokoff[i] = BLOCK_TOK;
        }
        P.nrm[0] = 4; P.nrm[1] = 3; P.nrm[2] = 1;
        P.tr[2] = 1; P.ldt[2] = S_TOK; P.stoff[2] = BLOCK_TOK;
        gemm_tc<true><<<dim3(D_MODEL / 128, CONDN / 128, 3), 256, GSM>>>(P, cosr, sinr);
    }
    // 4) fused attention: main (masked) + IP phase, LDSM operand loads
    {
        const int ASM = (2 * KSTW + 2 * VSTW + 128 * 68) * 4;   // 172032 B
        cudaFuncSetAttribute(attn_tc, cudaFuncAttributeMaxDynamicSharedMemorySize, ASM);
        attn_tc<<<dim3(S_TOK / 128, NHEAD), 256, ASM>>>(
            (const unsigned*)q, (const unsigned*)k, (const unsigned*)vt,
            (const unsigned*)kip, (const unsigned*)vipt, out);
    }
}

// round 11
// speedup vs baseline: 1.2440x; 1.0424x over previous
#include <cuda_runtime.h>

#define S_TOK     2304
#define D_MODEL   3072
#define NHEAD     24
#define HDIM      128
#define BLOCK_TOK 2048
#define CONDN     256
#define RANKN     128
#define T_IPN     128
#define D_IPN     4096
#define EPSV      1e-5f
// (1/sqrt(128)) * log2(e): softmax computed in exp2 domain
#define QSCALE    0.1275173e+0f
#define BIGROW    0x7fffffff

// ---------------- device scratch ----------------
__device__ float g_q[S_TOK * D_MODEL];
__device__ float g_k[S_TOK * D_MODEL];
__device__ float g_vt[D_MODEL * S_TOK];     // V transposed: [d 3072][tok 2304]
__device__ float g_kip[T_IPN * D_MODEL];
__device__ float g_vipt[D_MODEL * T_IPN];   // V_ip transposed
__device__ float g_lt[3 * CONDN * RANKN];
// RNA-tf32-rounded operand copies (GEMM loops fully cvt-free)
__device__ float g_xr[S_TOK * D_MODEL];
__device__ float g_wqr[D_MODEL * D_MODEL];
__device__ float g_wkr[D_MODEL * D_MODEL];
__device__ float g_wvr[D_MODEL * D_MODEL];
__device__ float g_imgr[T_IPN * D_IPN];
__device__ float g_wkipr[D_MODEL * D_IPN];
__device__ float g_wvipr[D_MODEL * D_IPN];
__device__ float g_ldr[6 * RANKN * D_MODEL];   // qd,kd,vd,qu,ku,vu rounded

// ---------------- helpers ----------------
__device__ __forceinline__ unsigned f2tf(float f) {
    unsigned u;
    asm("cvt.rna.tf32.f32 %0, %1;" : "=r"(u) : "f"(f));
    return u;
}
__device__ __forceinline__ void mma8(float* c, const unsigned* a, unsigned b0, unsigned b1) {
    asm volatile(
        "mma.sync.aligned.m16n8k8.row.col.f32.tf32.tf32.f32 "
        "{%0,%1,%2,%3}, {%4,%5,%6,%7}, {%8,%9}, {%0,%1,%2,%3};"
        : "+f"(c[0]), "+f"(c[1]), "+f"(c[2]), "+f"(c[3])
        : "r"(a[0]), "r"(a[1]), "r"(a[2]), "r"(a[3]), "r"(b0), "r"(b1));
}
__device__ __forceinline__ void ldsm4(unsigned* r, unsigned addr) {
    asm volatile("ldmatrix.sync.aligned.m8n8.x4.shared.b16 {%0,%1,%2,%3}, [%4];"
        : "=r"(r[0]), "=r"(r[1]), "=r"(r[2]), "=r"(r[3]) : "r"(addr));
}
__device__ __forceinline__ void cpa16(unsigned dst, const void* src) {
    asm volatile("cp.async.cg.shared.global [%0], [%1], 16;" :: "r"(dst), "l"(src));
}
__device__ __forceinline__ void cp_commit() { asm volatile("cp.async.commit_group;"); }
__device__ __forceinline__ void cp_wait0() { asm volatile("cp.async.wait_group 0;"); }
__device__ __forceinline__ void cp_wait1() { asm volatile("cp.async.wait_group 1;"); }

// ---------------- RNA tf32 rounding pre-pass (13 buffers) ----------------
struct R16 { const float* s[13]; float* d[13]; int n[13]; };
__global__ void round_tf32_kernel(R16 P) {
    const int y = blockIdx.y;
    const float4* src = (const float4*)P.s[y];
    float4* dst = (float4*)P.d[y];
    const int n4 = P.n[y] >> 2;
    for (int i = blockIdx.x * blockDim.x + threadIdx.x; i < n4; i += gridDim.x * blockDim.x) {
        float4 v = src[i];
        v.x = __uint_as_float(f2tf(v.x));
        v.y = __uint_as_float(f2tf(v.y));
        v.z = __uint_as_float(f2tf(v.z));
        v.w = __uint_as_float(f2tf(v.w));
        dst[i] = v;
    }
}

// ============ batched GEMM (cvt-free, LDSM operands, fused norm epilogue) ============
// C[M,N] (+)= A[M,K] @ B[N,K]^T + bias. All operands pre-rounded tf32 bit patterns.
// 128x128 tile, BK=16, 256 thr, warp tile 64x32, 3-stage cp.async, smem [mn][k] str 20.
// nrm: 0 raw, 1 round, 2 norm+round, 3 norm+w+rope+round, 4 = 3 + QSCALE.
// tr: store/ACC C transposed as C[col][ldt] at row stoff+r.
struct GemmB {
    const float* A[8]; const float* Bm[8]; const float* bias[8]; float* C[8];
    const float* w[8];
    int M[8], N[8], K[8], nrm[8], rowlim[8], tokoff[8], tr[8], ldt[8], stoff[8];
};

template <bool ACC>
__global__ __launch_bounds__(256, 2) void gemm_tc(GemmB P, const float* cs, const float* sn)
{
    extern __shared__ unsigned smg[];
    unsigned* As = smg;              // 3 stages x 2560
    unsigned* Bs = smg + 3 * 2560;   // 3 stages x 2560

    const int z = blockIdx.z;
    const int M = P.M[z], N = P.N[z], K = P.K[z];
    const int bm = blockIdx.y << 7, bn = blockIdx.x << 7;
    if (bm >= M || bn >= N) return;
    const float* A = P.A[z];
    const float* Bw = P.Bm[z];
    const float* bias = P.bias[z];
    float* C = P.C[z];
    const float* wp = P.w[z];
    const int mode = (bm >= P.rowlim[z]) ? 0 : P.nrm[z];
    const int tokoff = P.tokoff[z];
    const int tr = P.tr[z], ldt = P.ldt[z], stoff = P.stoff[z];

    const int tid = threadIdx.x;
    const int lw = tid & 31, w = tid >> 5, g = lw >> 2, t = lw & 3;
    const int wm = w & 1, wn = w >> 1;   // 2 x 4 warp grid, warp tile 64x32

    const int lrow = tid >> 1, lseg = (tid & 1) * 8;
    const float* Arow = A + (size_t)(bm + lrow) * K + lseg;
    const float* Brow = Bw + (size_t)(bn + lrow) * K + lseg;
    const unsigned as_u = (unsigned)__cvta_generic_to_shared(As) + (lrow * 20 + lseg) * 4;
    const unsigned bs_u = (unsigned)__cvta_generic_to_shared(Bs) + (lrow * 20 + lseg) * 4;

    // ldmatrix per-thread bases: A row = wm*64 + (l&7) + bit3*8, col = bit4*4
    //                            B row = wn*32 + (l&7) + bit4*8, col = bit3*4
    const int lr = lw & 7, lb3 = (lw >> 3) & 1, lb4 = lw >> 4;
    const unsigned a_ld = (unsigned)__cvta_generic_to_shared(As)
                        + (((wm * 64 + lr + lb3 * 8) * 20) + lb4 * 4) * 4;
    const unsigned b_ld = (unsigned)__cvta_generic_to_shared(Bs)
                        + (((wn * 32 + lr + lb4 * 8) * 20) + lb3 * 4) * 4;

    float acc[4][4][4];
#pragma unroll
    for (int mt = 0; mt < 4; mt++)
#pragma unroll
        for (int nt = 0; nt < 4; nt++)
#pragma unroll
            for (int i = 0; i < 4; i++) acc[mt][nt][i] = 0.f;

    const int niter = K >> 4;
    cpa16(as_u, Arow);              cpa16(as_u + 16, Arow + 4);
    cpa16(bs_u, Brow);              cpa16(bs_u + 16, Brow + 4);
    cp_commit();
    {
        const unsigned off = 2560u * 4u;
        cpa16(as_u + off, Arow + 16);   cpa16(as_u + off + 16, Arow + 20);
        cpa16(bs_u + off, Brow + 16);   cpa16(bs_u + off + 16, Brow + 20);
        cp_commit();
    }

    int st = 0, ld = 2;
    for (int it = 0; it < niter; it++) {
        if (it + 1 < niter) cp_wait1(); else cp_wait0();
        __syncthreads();
        if (it + 2 < niter) {
            const int k0 = (it + 2) << 4;
            const unsigned off = (unsigned)(ld * 2560 * 4);
            cpa16(as_u + off, Arow + k0);   cpa16(as_u + off + 16, Arow + k0 + 4);
            cpa16(bs_u + off, Brow + k0);   cpa16(bs_u + off + 16, Brow + k0 + 4);
            cp_commit();
            ld = (ld == 2) ? 0 : ld + 1;
        }
        const unsigned Ac = a_ld + (unsigned)(st * 2560 * 4);
        const unsigned Bc = b_ld + (unsigned)(st * 2560 * 4);
        st = (st == 2) ? 0 : st + 1;
#pragma unroll
        for (int ks = 0; ks < 2; ks++) {
            unsigned af[4][4], bf[4][2];
#pragma unroll
            for (int mt = 0; mt < 4; mt++)
                ldsm4(af[mt], Ac + (unsigned)((mt * 16 * 20 + ks * 8) * 4));
#pragma unroll
            for (int ntp = 0; ntp < 2; ntp++) {
                unsigned bb[4];
                ldsm4(bb, Bc + (unsigned)((ntp * 16 * 20 + ks * 8) * 4));
                bf[2 * ntp][0] = bb[0];     bf[2 * ntp][1] = bb[1];
                bf[2 * ntp + 1][0] = bb[2]; bf[2 * ntp + 1][1] = bb[3];
            }
#pragma unroll
            for (int mt = 0; mt < 4; mt++)
#pragma unroll
                for (int nt = 0; nt < 4; nt++)
                    mma8(acc[mt][nt], af[mt], bf[nt][0], bf[nt][1]);
        }
    }

    // ---- epilogue: bias/ACC ----
#pragma unroll
    for (int mt = 0; mt < 4; mt++) {
        const int r0 = bm + wm * 64 + mt * 16 + g;
        const int r1 = r0 + 8;
#pragma unroll
        for (int nt = 0; nt < 4; nt++) {
            const int cc = bn + wn * 32 + nt * 8 + 2 * t;
            if (bias) {
                float bx = bias[cc], by = bias[cc + 1];
                acc[mt][nt][0] += bx; acc[mt][nt][1] += by;
                acc[mt][nt][2] += bx; acc[mt][nt][3] += by;
            }
            if (ACC) {
                if (tr) {
                    acc[mt][nt][0] += C[(size_t)cc * ldt + stoff + r0];
                    acc[mt][nt][1] += C[(size_t)(cc + 1) * ldt + stoff + r0];
                    acc[mt][nt][2] += C[(size_t)cc * ldt + stoff + r1];
                    acc[mt][nt][3] += C[(size_t)(cc + 1) * ldt + stoff + r1];
                } else {
                    float2 e0 = *(const float2*)(C + (size_t)r0 * N + cc);
                    float2 e1 = *(const float2*)(C + (size_t)r1 * N + cc);
                    acc[mt][nt][0] += e0.x; acc[mt][nt][1] += e0.y;
                    acc[mt][nt][2] += e1.x; acc[mt][nt][3] += e1.y;
                }
            }
        }
    }

    float inv0[4], inv1[4];
    if (mode >= 2) {
        __syncthreads();
        float* ssb = (float*)smg;
#pragma unroll
        for (int mt = 0; mt < 4; mt++) {
            float s0 = 0.f, s1 = 0.f;
#pragma unroll
            for (int nt = 0; nt < 4; nt++) {
                s0 += acc[mt][nt][0] * acc[mt][nt][0] + acc[mt][nt][1] * acc[mt][nt][1];
                s1 += acc[mt][nt][2] * acc[mt][nt][2] + acc[mt][nt][3] * acc[mt][nt][3];
            }
            s0 += __shfl_xor_sync(0xffffffffu, s0, 1);
            s0 += __shfl_xor_sync(0xffffffffu, s0, 2);
            s1 += __shfl_xor_sync(0xffffffffu, s1, 1);
            s1 += __shfl_xor_sync(0xffffffffu, s1, 2);
            if (t == 0) {
                const int rr = wm * 64 + mt * 16 + g;
                ssb[rr * 4 + wn] = s0;
                ssb[(rr + 8) * 4 + wn] = s1;
            }
        }
        __syncthreads();
#pragma unroll
        for (int mt = 0; mt < 4; mt++) {
            const int rr = wm * 64 + mt * 16 + g;
            float4 a = ((const float4*)ssb)[rr];
            float4 b = ((const float4*)ssb)[rr + 8];
            inv0[mt] = rsqrtf((a.x + a.y + a.z + a.w) * (1.0f / HDIM) + EPSV);
            inv1[mt] = rsqrtf((b.x + b.y + b.z + b.w) * (1.0f / HDIM) + EPSV);
        }
    }

#pragma unroll
    for (int mt = 0; mt < 4; mt++) {
        const int r0 = bm + wm * 64 + mt * 16 + g;
        const int r1 = r0 + 8;
#pragma unroll
        for (int nt = 0; nt < 4; nt++) {
            const int d = wn * 32 + nt * 8 + 2 * t;
            const int cc = bn + d;
            float2 v0 = make_float2(acc[mt][nt][0], acc[mt][nt][1]);
            float2 v1 = make_float2(acc[mt][nt][2], acc[mt][nt][3]);
            if (mode >= 2) {
                v0.x *= inv0[mt]; v0.y *= inv0[mt];
                v1.x *= inv1[mt]; v1.y *= inv1[mt];
                if (wp) {
                    float2 ww = *(const float2*)(wp + d);
                    v0.x *= ww.x; v0.y *= ww.y;
                    v1.x *= ww.x; v1.y *= ww.y;
                }
            }
            if (mode >= 3) {
                const size_t t0 = (size_t)(tokoff + r0) * HDIM + d;
                const size_t t1 = (size_t)(tokoff + r1) * HDIM + d;
                float2 c0 = *(const float2*)(cs + t0);
                float2 s0v = *(const float2*)(sn + t0);
                float2 c1 = *(const float2*)(cs + t1);
                float2 s1v = *(const float2*)(sn + t1);
                float e0 = v0.x * c0.x - v0.y * s0v.x;
                float o0 = v0.y * c0.y + v0.x * s0v.y;
                float e1 = v1.x * c1.x - v1.y * s1v.x;
                float o1 = v1.y * c1.y + v1.x * s1v.y;
                v0.x = e0; v0.y = o0; v1.x = e1; v1.y = o1;
            }
            if (mode == 4) {
                v0.x *= QSCALE; v0.y *= QSCALE;
                v1.x *= QSCALE; v1.y *= QSCALE;
            }
            if (mode >= 1) {
                v0.x = __uint_as_float(f2tf(v0.x));
                v0.y = __uint_as_float(f2tf(v0.y));
                v1.x = __uint_as_float(f2tf(v1.x));
                v1.y = __uint_as_float(f2tf(v1.y));
            }
            if (tr) {
                C[(size_t)cc * ldt + stoff + r0] = v0.x;
                C[(size_t)(cc + 1) * ldt + stoff + r0] = v0.y;
                C[(size_t)cc * ldt + stoff + r1] = v1.x;
                C[(size_t)(cc + 1) * ldt + stoff + r1] = v1.y;
            } else {
                *(float2*)(C + (size_t)r0 * N + cc) = v0;
                *(float2*)(C + (size_t)r1 * N + cc) = v1;
            }
        }
    }
}

// ============ flash attention: Bq=128 x Bk=64, LDSM operand loads (R9 proven) ============
#define KSTW 8448   // 64*132
#define VSTW 8704   // 128*68
__global__ __launch_bounds__(256, 1) void attn_tc(
    const unsigned* __restrict__ Q, const unsigned* __restrict__ Km,
    const unsigned* __restrict__ Vtm, const unsigned* __restrict__ Ki,
    const unsigned* __restrict__ Vti, float* __restrict__ Out)
{
    extern __shared__ unsigned smu[];
    unsigned* Ks = smu;                        // [2][64][132]
    unsigned* Vs = smu + 2 * KSTW;             // [2][128][68]
    unsigned* Ps = smu + 2 * KSTW + 2 * VSTW;  // [128][68]

    const int tid = threadIdx.x;
    const int l = tid & 31, w = tid >> 5;
    const int g = l >> 2, t = l & 3;
    const int h = blockIdx.y;
    const int q0 = blockIdx.x << 7;
    const int qr = q0 + w * 16 + g;

    unsigned qf[16][4];
    {
        const unsigned* qp = Q + (size_t)qr * D_MODEL + h * HDIM;
        const unsigned* qp8 = qp + (size_t)8 * D_MODEL;
#pragma unroll
        for (int ks = 0; ks < 16; ks++) {
            const int cb = ks * 8 + t;
            qf[ks][0] = qp[cb];
            qf[ks][1] = qp8[cb];
            qf[ks][2] = qp[cb + 4];
            qf[ks][3] = qp8[cb + 4];
        }
    }

    const int krow = tid >> 2, kseg = (tid & 3) * 32;
    const int vrow = tid >> 1, vseg = (tid & 1) * 32;
    const unsigned ks_u = (unsigned)__cvta_generic_to_shared(Ks) + (krow * 132 + kseg) * 4;
    const unsigned vs_u = (unsigned)__cvta_generic_to_shared(Vs) + (vrow * 68 + vseg) * 4;

    const int lr = l & 7, lh = (l >> 3) & 1, lq = l >> 4;
    const unsigned kmat_u = (unsigned)__cvta_generic_to_shared(Ks) + ((lq * 8 + lr) * 132 + lh * 4) * 4;
    const unsigned vmat_u = (unsigned)__cvta_generic_to_shared(Vs) + ((lq * 8 + lr) * 68 + lh * 4) * 4;
    const unsigned pmat_u = (unsigned)__cvta_generic_to_shared(Ps) + ((w * 16 + lh * 8 + lr) * 68 + lq * 4) * 4;
    unsigned* Prow0 = Ps + (w * 16 + g) * 68 + 2 * t;
    unsigned* Prow1 = Prow0 + 8 * 68;

    float* op0 = Out + (size_t)qr * D_MODEL + h * HDIM;
    float* op1 = op0 + (size_t)8 * D_MODEL;

#pragma unroll 1
    for (int ph = 0; ph < 2; ph++) {
        const unsigned* Kb = ph ? Ki : Km;
        const unsigned* Vb = ph ? Vti : Vtm;
        const int toks = ph ? T_IPN : S_TOK;
        const int kt0 = (ph == 0 && q0 >= BLOCK_TOK) ? BLOCK_TOK : 0;
        const int ntiles = (toks - kt0) >> 6;

        float o[16][4];
#pragma unroll
        for (int nt = 0; nt < 16; nt++)
#pragma unroll
            for (int i = 0; i < 4; i++) o[nt][i] = 0.f;
        float mrow0 = -1e30f, mrow1 = -1e30f, lrow0 = 0.f, lrow1 = 0.f;

        __syncthreads();
        {
            const unsigned* kg = Kb + (size_t)(kt0 + krow) * D_MODEL + h * HDIM + kseg;
            const unsigned* vg = Vb + (size_t)(h * HDIM + vrow) * toks + kt0 + vseg;
#pragma unroll
            for (int c = 0; c < 8; c++) {
                cpa16(ks_u + c * 16, kg + c * 4);
                cpa16(vs_u + c * 16, vg + c * 4);
            }
            cp_commit();
        }

        for (int it = 0; it < ntiles; it++) {
            const int cur = it & 1;
            cp_wait0();
            __syncthreads();
            if (it + 1 < ntiles) {
                const int kt = kt0 + (it + 1) * 64;
                const unsigned* kg = Kb + (size_t)(kt + krow) * D_MODEL + h * HDIM + kseg;
                const unsigned* vg = Vb + (size_t)(h * HDIM + vrow) * toks + kt + vseg;
                const unsigned ko = ks_u + (cur ^ 1) * KSTW * 4;
                const unsigned vo = vs_u + (cur ^ 1) * VSTW * 4;
#pragma unroll
                for (int c = 0; c < 8; c++) {
                    cpa16(ko + c * 16, kg + c * 4);
                    cpa16(vo + c * 16, vg + c * 4);
                }
                cp_commit();
            }
            const unsigned Kc_u = kmat_u + cur * KSTW * 4;
            const unsigned Vc_u = vmat_u + cur * VSTW * 4;

            float s[8][4];
#pragma unroll
            for (int nt = 0; nt < 8; nt++)
#pragma unroll
                for (int i = 0; i < 4; i++) s[nt][i] = 0.f;
#pragma unroll
            for (int ks = 0; ks < 16; ks++) {
#pragma unroll
                for (int ntp = 0; ntp < 4; ntp++) {
                    unsigned b[4];
                    ldsm4(b, Kc_u + (unsigned)((ntp * 16 * 132 + ks * 8) * 4));
                    mma8(s[ntp * 2],     qf[ks], b[0], b[1]);
                    mma8(s[ntp * 2 + 1], qf[ks], b[2], b[3]);
                }
            }

            float mx0 = -1e30f, mx1 = -1e30f;
#pragma unroll
            for (int nt = 0; nt < 8; nt++) {
                mx0 = fmaxf(mx0, fmaxf(s[nt][0], s[nt][1]));
                mx1 = fmaxf(mx1, fmaxf(s[nt][2], s[nt][3]));
            }
            mx0 = fmaxf(mx0, __shfl_xor_sync(0xffffffffu, mx0, 1));
            mx0 = fmaxf(mx0, __shfl_xor_sync(0xffffffffu, mx0, 2));
            mx1 = fmaxf(mx1, __shfl_xor_sync(0xffffffffu, mx1, 1));
            mx1 = fmaxf(mx1, __shfl_xor_sync(0xffffffffu, mx1, 2));
            const float mn0 = fmaxf(mrow0, mx0), mn1 = fmaxf(mrow1, mx1);
            const float al0 = exp2f(mrow0 - mn0), al1 = exp2f(mrow1 - mn1);
            mrow0 = mn0; mrow1 = mn1;

            float sum0 = 0.f, sum1 = 0.f;
#pragma unroll
            for (int nt = 0; nt < 8; nt++) {
                float p0 = exp2f(s[nt][0] - mn0);
                float p1 = exp2f(s[nt][1] - mn0);
                float p2 = exp2f(s[nt][2] - mn1);
                float p3 = exp2f(s[nt][3] - mn1);
                sum0 += p0 + p1;
                sum1 += p2 + p3;
                *(uint2*)(Prow0 + nt * 8) = make_uint2(f2tf(p0), f2tf(p1));
                *(uint2*)(Prow1 + nt * 8) = make_uint2(f2tf(p2), f2tf(p3));
            }
            sum0 += __shfl_xor_sync(0xffffffffu, sum0, 1);
            sum0 += __shfl_xor_sync(0xffffffffu, sum0, 2);
            sum1 += __shfl_xor_sync(0xffffffffu, sum1, 1);
            sum1 += __shfl_xor_sync(0xffffffffu, sum1, 2);
            lrow0 = lrow0 * al0 + sum0;
            lrow1 = lrow1 * al1 + sum1;
#pragma unroll
            for (int nt = 0; nt < 16; nt++) {
                o[nt][0] *= al0; o[nt][1] *= al0;
                o[nt][2] *= al1; o[nt][3] *= al1;
            }
            __syncwarp();

#pragma unroll
            for (int ks = 0; ks < 8; ks++) {
                unsigned pa[4];
                ldsm4(pa, pmat_u + (unsigned)(ks * 8 * 4));
#pragma unroll
                for (int ntp = 0; ntp < 8; ntp++) {
                    unsigned b[4];
                    ldsm4(b, Vc_u + (unsigned)((ntp * 16 * 68 + ks * 8) * 4));
                    mma8(o[ntp * 2],     pa, b[0], b[1]);
                    mma8(o[ntp * 2 + 1], pa, b[2], b[3]);
                }
            }
            __syncwarp();
        }

        const float inv0 = 1.f / lrow0, inv1 = 1.f / lrow1;
#pragma unroll
        for (int nt = 0; nt < 16; nt++) {
            const int cc = nt * 8 + 2 * t;
            float2 v0 = make_float2(o[nt][0] * inv0, o[nt][1] * inv0);
            float2 v1 = make_float2(o[nt][2] * inv1, o[nt][3] * inv1);
            if (ph == 1) {
                float2 e0 = *(const float2*)(op0 + cc);
                float2 e1 = *(const float2*)(op1 + cc);
                v0.x += e0.x; v0.y += e0.y; v1.x += e1.x; v1.y += e1.y;
            }
            *(float2*)(op0 + cc) = v0;
            *(float2*)(op1 + cc) = v1;
        }
    }
}

// ---------------- host launcher ----------------
extern "C" void kernel_launch(void* const* d_in, const int* in_sizes, int n_in,
                              void* d_out, int out_size)
{
    (void)in_sizes; (void)n_in; (void)out_size;
    const float* x    = (const float*)d_in[0];
    const float* img  = (const float*)d_in[1];
    const float* cosr = (const float*)d_in[2];
    const float* sinr = (const float*)d_in[3];
    const float* Wq   = (const float*)d_in[4];
    const float* bq   = (const float*)d_in[5];
    const float* Wk   = (const float*)d_in[6];
    const float* bk   = (const float*)d_in[7];
    const float* Wv   = (const float*)d_in[8];
    const float* bv   = (const float*)d_in[9];
    const float* qd   = (const float*)d_in[10];
    const float* qu   = (const float*)d_in[11];
    const float* kd   = (const float*)d_in[12];
    const float* ku   = (const float*)d_in[13];
    const float* vd   = (const float*)d_in[14];
    const float* vu   = (const float*)d_in[15];
    const float* nqw  = (const float*)d_in[16];
    const float* nkw  = (const float*)d_in[17];
    const float* Wkip = (const float*)d_in[18];
    const float* Wvip = (const float*)d_in[19];
    float* out = (float*)d_out;

    float *q, *k, *vt, *kip, *vipt, *lt;
    float *xr, *wqr, *wkr, *wvr, *imgr, *wkipr, *wvipr, *ldr;
    cudaGetSymbolAddress((void**)&q,     g_q);
    cudaGetSymbolAddress((void**)&k,     g_k);
    cudaGetSymbolAddress((void**)&vt,    g_vt);
    cudaGetSymbolAddress((void**)&kip,   g_kip);
    cudaGetSymbolAddress((void**)&vipt,  g_vipt);
    cudaGetSymbolAddress((void**)&lt,    g_lt);
    cudaGetSymbolAddress((void**)&xr,    g_xr);
    cudaGetSymbolAddress((void**)&wqr,   g_wqr);
    cudaGetSymbolAddress((void**)&wkr,   g_wkr);
    cudaGetSymbolAddress((void**)&wvr,   g_wvr);
    cudaGetSymbolAddress((void**)&imgr,  g_imgr);
    cudaGetSymbolAddress((void**)&wkipr, g_wkipr);
    cudaGetSymbolAddress((void**)&wvipr, g_wvipr);
    cudaGetSymbolAddress((void**)&ldr,   g_ldr);

    const int LW = RANKN * D_MODEL;
    float* qdr = ldr;            float* kdr = ldr + LW;     float* vdr = ldr + 2 * LW;
    float* qur = ldr + 3 * LW;   float* kur = ldr + 4 * LW; float* vur = ldr + 5 * LW;

    const int GSM = 6 * 2560 * 4;
    cudaFuncSetAttribute(gemm_tc<false>, cudaFuncAttributeMaxDynamicSharedMemorySize, GSM);
    cudaFuncSetAttribute(gemm_tc<true>,  cudaFuncAttributeMaxDynamicSharedMemorySize, GSM);

    // 1) RNA tf32 rounding pre-pass (13 buffers)
    {
        R16 R;
        R.s[0]  = x;    R.d[0]  = xr;    R.n[0]  = S_TOK * D_MODEL;
        R.s[1]  = Wq;   R.d[1]  = wqr;   R.n[1]  = D_MODEL * D_MODEL;
        R.s[2]  = Wk;   R.d[2]  = wkr;   R.n[2]  = D_MODEL * D_MODEL;
        R.s[3]  = Wv;   R.d[3]  = wvr;   R.n[3]  = D_MODEL * D_MODEL;
        R.s[4]  = img;  R.d[4]  = imgr;  R.n[4]  = T_IPN * D_IPN;
        R.s[5]  = Wkip; R.d[5]  = wkipr; R.n[5]  = D_MODEL * D_IPN;
        R.s[6]  = Wvip; R.d[6]  = wvipr; R.n[6]  = D_MODEL * D_IPN;
        R.s[7]  = qd;   R.d[7]  = qdr;   R.n[7]  = LW;
        R.s[8]  = kd;   R.d[8]  = kdr;   R.n[8]  = LW;
        R.s[9]  = vd;   R.d[9]  = vdr;   R.n[9]  = LW;
        R.s[10] = qu;   R.d[10] = qur;   R.n[10] = LW;
        R.s[11] = ku;   R.d[11] = kur;   R.n[11] = LW;
        R.s[12] = vu;   R.d[12] = vur;   R.n[12] = LW;
        round_tf32_kernel<<<dim3(512, 13), 256>>>(R);
    }
    const float* xcr = xr + (size_t)BLOCK_TOK * D_MODEL;

    // 2) mega GEMM: z0-2 QKV (V transposed out), z3-5 LoRA-down, z6-7 IP proj
    {
        GemmB P;
        for (int i = 0; i < 8; i++) { P.tr[i] = 0; P.ldt[i] = 1; P.stoff[i] = 0; P.tokoff[i] = 0; P.w[i] = nullptr; }
        P.A[0] = xr; P.A[1] = xr; P.A[2] = xr;
        P.Bm[0] = wqr; P.Bm[1] = wkr; P.Bm[2] = wvr;
        P.bias[0] = bq; P.bias[1] = bk; P.bias[2] = bv;
        P.C[0] = q;  P.C[1] = k;  P.C[2] = vt;
        P.w[0] = nqw; P.w[1] = nkw;
        P.M[0] = P.M[1] = P.M[2] = S_TOK;
        P.N[0] = P.N[1] = P.N[2] = D_MODEL;
        P.K[0] = P.K[1] = P.K[2] = D_MODEL;
        P.nrm[0] = 4; P.nrm[1] = 3; P.nrm[2] = 1;
        P.rowlim[0] = P.rowlim[1] = P.rowlim[2] = BLOCK_TOK;
        P.tr[2] = 1; P.ldt[2] = S_TOK; P.stoff[2] = 0;
        P.A[3] = xcr; P.A[4] = xcr; P.A[5] = xcr;
        P.Bm[3] = qdr; P.Bm[4] = kdr; P.Bm[5] = vdr;
        P.bias[3] = P.bias[4] = P.bias[5] = nullptr;
        P.C[3] = lt; P.C[4] = lt + CONDN * RANKN; P.C[5] = lt + 2 * CONDN * RANKN;
        P.M[3] = P.M[4] = P.M[5] = CONDN;
        P.N[3] = P.N[4] = P.N[5] = RANKN;
        P.K[3] = P.K[4] = P.K[5] = D_MODEL;
        P.nrm[3] = P.nrm[4] = P.nrm[5] = 1;
        P.rowlim[3] = P.rowlim[4] = P.rowlim[5] = BIGROW;
        P.A[6] = imgr; P.A[7] = imgr;
        P.Bm[6] = wkipr; P.Bm[7] = wvipr;
        P.bias[6] = P.bias[7] = nullptr;
        P.C[6] = kip; P.C[7] = vipt;
        P.M[6] = P.M[7] = T_IPN;
        P.N[6] = P.N[7] = D_MODEL;
        P.K[6] = P.K[7] = D_IPN;
        P.nrm[6] = 2; P.nrm[7] = 1;
        P.rowlim[6] = P.rowlim[7] = BIGROW;
        P.tr[7] = 1; P.ldt[7] = T_IPN; P.stoff[7] = 0;
        gemm_tc<false><<<dim3(D_MODEL / 128, S_TOK / 128, 8), 256, GSM>>>(P, cosr, sinr);
    }
    // 3) LoRA up: accumulate into q/k/vt cond rows, fused norm+rope+round
    {
        GemmB P;
        for (int i = 0; i < 8; i++) {
            P.A[i] = nullptr; P.Bm[i] = nullptr; P.bias[i] = nullptr; P.C[i] = nullptr;
            P.w[i] = nullptr; P.M[i] = 0; P.N[i] = 0; P.K[i] = 16;
            P.nrm[i] = 0; P.rowlim[i] = BIGROW; P.tokoff[i] = 0;
            P.tr[i] = 0; P.ldt[i] = 1; P.stoff[i] = 0;
        }
        P.A[0] = lt; P.A[1] = lt + CONDN * RANKN; P.A[2] = lt + 2 * CONDN * RANKN;
        P.Bm[0] = qur; P.Bm[1] = kur; P.Bm[2] = vur;
        P.C[0] = q + (size_t)BLOCK_TOK * D_MODEL;
        P.C[1] = k + (size_t)BLOCK_TOK * D_MODEL;
        P.C[2] = vt;
        P.w[0] = nqw; P.w[1] = nkw;
        for (int i = 0; i < 3; i++) {
            P.M[i] = CONDN; P.N[i] = D_MODEL; P.K[i] = RANKN;
            P.tokoff[i] = BLOCK_TOK;
        }
        P.nrm[0] = 4; P.nrm[1] = 3; P.nrm[2] = 1;
        P.tr[2] = 1; P.ldt[2] = S_TOK; P.stoff[2] = BLOCK_TOK;
        gemm_tc<true><<<dim3(D_MODEL / 128, CONDN / 128, 3), 256, GSM>>>(P, cosr, sinr);
    }
    // 4) fused attention: main (masked) + IP phase, LDSM operand loads
    {
        const int ASM = (2 * KSTW + 2 * VSTW + 128 * 68) * 4;   // 172032 B
        cudaFuncSetAttribute(attn_tc, cudaFuncAttributeMaxDynamicSharedMemorySize, ASM);
        attn_tc<<<dim3(S_TOK / 128, NHEAD), 256, ASM>>>(
            (const unsigned*)q, (const unsigned*)k, (const unsigned*)vt,
            (const unsigned*)kip, (const unsigned*)vipt, out);
    }
}

// round 12
// speedup vs baseline: 2.3358x; 1.8776x over previous
#include <cuda_runtime.h>
#include <cuda_fp16.h>

#define S_TOK     2304
#define D_MODEL   3072
#define NHEAD     24
#define HDIM      128
#define BLOCK_TOK 2048
#define CONDN     256
#define RANKN     128
#define T_IPN     128
#define D_IPN     4096
#define EPSV      1e-5f
// (1/sqrt(128)) * log2(e): softmax computed in exp2 domain
#define QSCALE    0.1275173e+0f
#define BIGROW    0x7fffffff

// ---------------- device scratch (fp16 operands, fp32 staging) ----------------
__device__ __half g_q[S_TOK * D_MODEL];
__device__ __half g_k[S_TOK * D_MODEL];
__device__ __half g_vt[D_MODEL * S_TOK];     // V transposed: [d][tok]
__device__ __half g_kip[T_IPN * D_MODEL];
__device__ __half g_vipt[D_MODEL * T_IPN];
__device__ __half g_lt[3 * CONDN * RANKN];
__device__ __half g_xr[S_TOK * D_MODEL];
__device__ __half g_wqr[D_MODEL * D_MODEL];
__device__ __half g_wkr[D_MODEL * D_MODEL];
__device__ __half g_wvr[D_MODEL * D_MODEL];
__device__ __half g_imgr[T_IPN * D_IPN];
__device__ __half g_wkipr[D_MODEL * D_IPN];
__device__ __half g_wvipr[D_MODEL * D_IPN];
__device__ __half g_ldr[6 * RANKN * D_MODEL];
__device__ float  g_stage[3 * CONDN * D_MODEL];   // fp32 cond-row staging (q,k,v)

// ---------------- helpers ----------------
__device__ __forceinline__ unsigned h2pack(float a, float b) {
    __half2 h = __floats2half2_rn(a, b);
    return *(unsigned*)&h;
}
__device__ __forceinline__ void mma16(float* c, const unsigned* a, unsigned b0, unsigned b1) {
    asm volatile(
        "mma.sync.aligned.m16n8k16.row.col.f32.f16.f16.f32 "
        "{%0,%1,%2,%3}, {%4,%5,%6,%7}, {%8,%9}, {%0,%1,%2,%3};"
        : "+f"(c[0]), "+f"(c[1]), "+f"(c[2]), "+f"(c[3])
        : "r"(a[0]), "r"(a[1]), "r"(a[2]), "r"(a[3]), "r"(b0), "r"(b1));
}
__device__ __forceinline__ void ldsm4(unsigned* r, unsigned addr) {
    asm volatile("ldmatrix.sync.aligned.m8n8.x4.shared.b16 {%0,%1,%2,%3}, [%4];"
        : "=r"(r[0]), "=r"(r[1]), "=r"(r[2]), "=r"(r[3]) : "r"(addr));
}
__device__ __forceinline__ void cpa16(unsigned dst, const void* src) {
    asm volatile("cp.async.cg.shared.global [%0], [%1], 16;" :: "r"(dst), "l"(src));
}
__device__ __forceinline__ void cp_commit() { asm volatile("cp.async.commit_group;"); }
__device__ __forceinline__ void cp_wait0() { asm volatile("cp.async.wait_group 0;"); }
__device__ __forceinline__ void cp_wait1() { asm volatile("cp.async.wait_group 1;"); }

// ---------------- fp16 rounding pre-pass (13 buffers) ----------------
struct R16 { const float* s[13]; __half* d[13]; int n[13]; };
__global__ void round_h_kernel(R16 P) {
    const int y = blockIdx.y;
    const float4* src = (const float4*)P.s[y];
    uint2* dst = (uint2*)P.d[y];
    const int n4 = P.n[y] >> 2;
    for (int i = blockIdx.x * blockDim.x + threadIdx.x; i < n4; i += gridDim.x * blockDim.x) {
        float4 v = src[i];
        uint2 o;
        o.x = h2pack(v.x, v.y);
        o.y = h2pack(v.z, v.w);
        dst[i] = o;
    }
}

// ============ batched fp16 GEMM (LDSM, m16n8k16, fused norm epilogue) ============
// C[M,N] (+)= A[M,K] @ B[N,K]^T + bias. 128x128 tile, BK=32, 256 thr, warp 64x32,
// 3-stage cp.async, smem half[mn][40] (80B rows, conflict-free).
// nrm: 0 raw->fp32 stage, 1 ->fp16, 2 norm, 3 norm+w+rope, 4 = 3+QSCALE.
// tr: store C transposed C[col][ldt] at row stoff+r (fp16).
struct GemmB {
    const __half* A[8]; const __half* Bm[8]; const float* bias[8];
    __half* C[8]; float* Cst[8]; const float* accs[8];
    const float* w[8];
    int M[8], N[8], K[8], nrm[8], rowlim[8], tokoff[8], tr[8], ldt[8], stoff[8];
};

template <bool ACC>
__global__ __launch_bounds__(256, 2) void gemm_tc(GemmB P, const float* cs, const float* sn)
{
    extern __shared__ __half smg[];
    __half* As = smg;              // 3 stages x 128*40
    __half* Bs = smg + 3 * 5120;

    const int z = blockIdx.z;
    const int M = P.M[z], N = P.N[z], K = P.K[z];
    const int bm = blockIdx.y << 7, bn = blockIdx.x << 7;
    if (bm >= M || bn >= N) return;
    const __half* A = P.A[z];
    const __half* Bw = P.Bm[z];
    const float* bias = P.bias[z];
    __half* C = P.C[z];
    float* Cst = P.Cst[z];
    const float* accs = P.accs[z];
    const float* wp = P.w[z];
    const int rowlim = P.rowlim[z];
    const int mode = (bm >= rowlim) ? 0 : P.nrm[z];
    const int tokoff = P.tokoff[z];
    const int tr = P.tr[z], ldt = P.ldt[z], stoff = P.stoff[z];

    const int tid = threadIdx.x;
    const int lw = tid & 31, w = tid >> 5, g = lw >> 2, t = lw & 3;
    const int wm = w & 1, wn = w >> 1;   // warp tile 64x32

    const int lrow = tid >> 1, lseg = (tid & 1) * 16;     // 16 halves = 32B
    const __half* Arow = A + (size_t)(bm + lrow) * K + lseg;
    const __half* Brow = Bw + (size_t)(bn + lrow) * K + lseg;
    const unsigned as_u = (unsigned)__cvta_generic_to_shared(As) + (lrow * 40 + lseg) * 2;
    const unsigned bs_u = (unsigned)__cvta_generic_to_shared(Bs) + (lrow * 40 + lseg) * 2;

    const int lr = lw & 7, lb3 = (lw >> 3) & 1, lb4 = lw >> 4;
    const unsigned a_ld = (unsigned)__cvta_generic_to_shared(As)
                        + ((wm * 64 + lr + lb3 * 8) * 40 + lb4 * 8) * 2;
    const unsigned b_ld = (unsigned)__cvta_generic_to_shared(Bs)
                        + ((wn * 32 + lr + lb4 * 8) * 40 + lb3 * 8) * 2;

    float acc[4][4][4];
#pragma unroll
    for (int mt = 0; mt < 4; mt++)
#pragma unroll
        for (int nt = 0; nt < 4; nt++)
#pragma unroll
            for (int i = 0; i < 4; i++) acc[mt][nt][i] = 0.f;

    const int niter = K >> 5;
    cpa16(as_u, Arow);              cpa16(as_u + 16, Arow + 8);
    cpa16(bs_u, Brow);              cpa16(bs_u + 16, Brow + 8);
    cp_commit();
    {
        const unsigned off = 5120u * 2u;
        cpa16(as_u + off, Arow + 32);   cpa16(as_u + off + 16, Arow + 40);
        cpa16(bs_u + off, Brow + 32);   cpa16(bs_u + off + 16, Brow + 40);
        cp_commit();
    }

    int st = 0, ld = 2;
    for (int it = 0; it < niter; it++) {
        if (it + 1 < niter) cp_wait1(); else cp_wait0();
        __syncthreads();
        if (it + 2 < niter) {
            const int k0 = (it + 2) << 5;
            const unsigned off = (unsigned)(ld * 5120 * 2);
            cpa16(as_u + off, Arow + k0);   cpa16(as_u + off + 16, Arow + k0 + 8);
            cpa16(bs_u + off, Brow + k0);   cpa16(bs_u + off + 16, Brow + k0 + 8);
            cp_commit();
            ld = (ld == 2) ? 0 : ld + 1;
        }
        const unsigned Ac = a_ld + (unsigned)(st * 5120 * 2);
        const unsigned Bc = b_ld + (unsigned)(st * 5120 * 2);
        st = (st == 2) ? 0 : st + 1;
#pragma unroll
        for (int ks = 0; ks < 2; ks++) {
            unsigned af[4][4], bf[4][2];
#pragma unroll
            for (int mt = 0; mt < 4; mt++)
                ldsm4(af[mt], Ac + (unsigned)((mt * 16 * 40 + ks * 16) * 2));
#pragma unroll
            for (int ntp = 0; ntp < 2; ntp++) {
                unsigned bb[4];
                ldsm4(bb, Bc + (unsigned)((ntp * 16 * 40 + ks * 16) * 2));
                bf[2 * ntp][0] = bb[0];     bf[2 * ntp][1] = bb[1];
                bf[2 * ntp + 1][0] = bb[2]; bf[2 * ntp + 1][1] = bb[3];
            }
#pragma unroll
            for (int mt = 0; mt < 4; mt++)
#pragma unroll
                for (int nt = 0; nt < 4; nt++)
                    mma16(acc[mt][nt], af[mt], bf[nt][0], bf[nt][1]);
        }
    }

    // ---- bias / fp32 accumulate-source ----
#pragma unroll
    for (int mt = 0; mt < 4; mt++) {
        const int r0 = bm + wm * 64 + mt * 16 + g;
        const int r1 = r0 + 8;
#pragma unroll
        for (int nt = 0; nt < 4; nt++) {
            const int cc = bn + wn * 32 + nt * 8 + 2 * t;
            if (bias) {
                float bx = bias[cc], by = bias[cc + 1];
                acc[mt][nt][0] += bx; acc[mt][nt][1] += by;
                acc[mt][nt][2] += bx; acc[mt][nt][3] += by;
            }
            if (ACC) {
                float2 e0 = *(const float2*)(accs + (size_t)r0 * N + cc);
                float2 e1 = *(const float2*)(accs + (size_t)r1 * N + cc);
                acc[mt][nt][0] += e0.x; acc[mt][nt][1] += e0.y;
                acc[mt][nt][2] += e1.x; acc[mt][nt][3] += e1.y;
            }
        }
    }

    float inv0[4], inv1[4];
    if (mode >= 2) {
        __syncthreads();
        float* ssb = (float*)smg;
#pragma unroll
        for (int mt = 0; mt < 4; mt++) {
            float s0 = 0.f, s1 = 0.f;
#pragma unroll
            for (int nt = 0; nt < 4; nt++) {
                s0 += acc[mt][nt][0] * acc[mt][nt][0] + acc[mt][nt][1] * acc[mt][nt][1];
                s1 += acc[mt][nt][2] * acc[mt][nt][2] + acc[mt][nt][3] * acc[mt][nt][3];
            }
            s0 += __shfl_xor_sync(0xffffffffu, s0, 1);
            s0 += __shfl_xor_sync(0xffffffffu, s0, 2);
            s1 += __shfl_xor_sync(0xffffffffu, s1, 1);
            s1 += __shfl_xor_sync(0xffffffffu, s1, 2);
            if (t == 0) {
                const int rr = wm * 64 + mt * 16 + g;
                ssb[rr * 4 + wn] = s0;
                ssb[(rr + 8) * 4 + wn] = s1;
            }
        }
        __syncthreads();
#pragma unroll
        for (int mt = 0; mt < 4; mt++) {
            const int rr = wm * 64 + mt * 16 + g;
            float4 a = ((const float4*)ssb)[rr];
            float4 b = ((const float4*)ssb)[rr + 8];
            inv0[mt] = rsqrtf((a.x + a.y + a.z + a.w) * (1.0f / HDIM) + EPSV);
            inv1[mt] = rsqrtf((b.x + b.y + b.z + b.w) * (1.0f / HDIM) + EPSV);
        }
    }

#pragma unroll
    for (int mt = 0; mt < 4; mt++) {
        const int r0 = bm + wm * 64 + mt * 16 + g;
        const int r1 = r0 + 8;
#pragma unroll
        for (int nt = 0; nt < 4; nt++) {
            const int d = wn * 32 + nt * 8 + 2 * t;
            const int cc = bn + d;
            float2 v0 = make_float2(acc[mt][nt][0], acc[mt][nt][1]);
            float2 v1 = make_float2(acc[mt][nt][2], acc[mt][nt][3]);
            if (mode == 0) {
                // raw cond rows -> fp32 staging
                *(float2*)(Cst + (size_t)(r0 - rowlim) * N + cc) = v0;
                *(float2*)(Cst + (size_t)(r1 - rowlim) * N + cc) = v1;
                continue;
            }
            if (mode >= 2) {
                v0.x *= inv0[mt]; v0.y *= inv0[mt];
                v1.x *= inv1[mt]; v1.y *= inv1[mt];
                if (wp) {
                    float2 ww = *(const float2*)(wp + d);
                    v0.x *= ww.x; v0.y *= ww.y;
                    v1.x *= ww.x; v1.y *= ww.y;
                }
            }
            if (mode >= 3) {
                const size_t t0 = (size_t)(tokoff + r0) * HDIM + d;
                const size_t t1 = (size_t)(tokoff + r1) * HDIM + d;
                float2 c0 = *(const float2*)(cs + t0);
                float2 s0v = *(const float2*)(sn + t0);
                float2 c1 = *(const float2*)(cs + t1);
                float2 s1v = *(const float2*)(sn + t1);
                float e0 = v0.x * c0.x - v0.y * s0v.x;
                float o0 = v0.y * c0.y + v0.x * s0v.y;
                float e1 = v1.x * c1.x - v1.y * s1v.x;
                float o1 = v1.y * c1.y + v1.x * s1v.y;
                v0.x = e0; v0.y = o0; v1.x = e1; v1.y = o1;
            }
            if (mode == 4) {
                v0.x *= QSCALE; v0.y *= QSCALE;
                v1.x *= QSCALE; v1.y *= QSCALE;
            }
            if (tr) {
                C[(size_t)cc * ldt + stoff + r0] = __float2half_rn(v0.x);
                C[(size_t)(cc + 1) * ldt + stoff + r0] = __float2half_rn(v0.y);
                C[(size_t)cc * ldt + stoff + r1] = __float2half_rn(v1.x);
                C[(size_t)(cc + 1) * ldt + stoff + r1] = __float2half_rn(v1.y);
            } else {
                *(unsigned*)(C + (size_t)r0 * N + cc) = h2pack(v0.x, v0.y);
                *(unsigned*)(C + (size_t)r1 * N + cc) = h2pack(v1.x, v1.y);
            }
        }
    }
}

// ============ flash attention, fp16 m16n8k16, Bq=128 x Bk=64, LDSM ============
// K smem [kv 64][136 halves]; Vt smem [d 128][72]; P smem [q 128][72].
#define KST_H 8704    // 64*136 halves
#define VST_H 9216    // 128*72 halves
__global__ __launch_bounds__(256, 1) void attn_tc(
    const __half* __restrict__ Q, const __half* __restrict__ Km,
    const __half* __restrict__ Vtm, const __half* __restrict__ Ki,
    const __half* __restrict__ Vti, float* __restrict__ Out)
{
    extern __shared__ __half smh[];
    __half* Ks = smh;                          // [2][64][136]
    __half* Vs = smh + 2 * KST_H;              // [2][128][72]
    unsigned* Ps32 = (unsigned*)(smh + 2 * KST_H + 2 * VST_H);  // [128][36] u32

    const int tid = threadIdx.x;
    const int l = tid & 31, w = tid >> 5;
    const int g = l >> 2, t = l & 3;
    const int h = blockIdx.y;
    const int q0 = blockIdx.x << 7;
    const int qr = q0 + w * 16 + g;

    // Q a-frags (fp16x2 packed, pre-scaled): 8 k16 steps
    unsigned qf[8][4];
    {
        const unsigned* qp  = (const unsigned*)(Q + (size_t)qr * D_MODEL + h * HDIM);
        const unsigned* qp8 = (const unsigned*)(Q + (size_t)(qr + 8) * D_MODEL + h * HDIM);
#pragma unroll
        for (int ks = 0; ks < 8; ks++) {
            qf[ks][0] = qp[8 * ks + t];
            qf[ks][1] = qp8[8 * ks + t];
            qf[ks][2] = qp[8 * ks + 4 + t];
            qf[ks][3] = qp8[8 * ks + 4 + t];
        }
    }

    // tile-fill mappings
    const int krow = tid >> 2, kseg = (tid & 3) * 32;   // K: 4 thr/row, 64B each
    const int vrow = tid >> 1, vseg = (tid & 1) * 32;   // V: 2 thr/row, 64B each
    const unsigned ks_u = (unsigned)__cvta_generic_to_shared(Ks) + (krow * 136 + kseg) * 2;
    const unsigned vs_u = (unsigned)__cvta_generic_to_shared(Vs) + (vrow * 72 + vseg) * 2;

    const int lr = l & 7, lh = (l >> 3) & 1, lq = l >> 4;
    const unsigned kmat_u = (unsigned)__cvta_generic_to_shared(Ks) + ((lq * 8 + lr) * 136 + lh * 8) * 2;
    const unsigned vmat_u = (unsigned)__cvta_generic_to_shared(Vs) + ((lq * 8 + lr) * 72 + lh * 8) * 2;
    const unsigned pmat_u = (unsigned)__cvta_generic_to_shared(Ps32) + (((w * 16 + lr + lh * 8) * 36 + lq * 4)) * 4;
    unsigned* Prow0 = Ps32 + (w * 16 + g) * 36 + t;
    unsigned* Prow1 = Prow0 + 8 * 36;

    float* op0 = Out + (size_t)qr * D_MODEL + h * HDIM;
    float* op1 = op0 + (size_t)8 * D_MODEL;

#pragma unroll 1
    for (int ph = 0; ph < 2; ph++) {
        const __half* Kb = ph ? Ki : Km;
        const __half* Vb = ph ? Vti : Vtm;
        const int toks = ph ? T_IPN : S_TOK;
        const int kt0 = (ph == 0 && q0 >= BLOCK_TOK) ? BLOCK_TOK : 0;
        const int ntiles = (toks - kt0) >> 6;

        float o[16][4];
#pragma unroll
        for (int nt = 0; nt < 16; nt++)
#pragma unroll
            for (int i = 0; i < 4; i++) o[nt][i] = 0.f;
        float mrow0 = -1e30f, mrow1 = -1e30f, lrow0 = 0.f, lrow1 = 0.f;

        __syncthreads();
        {
            const __half* kg = Kb + (size_t)(kt0 + krow) * D_MODEL + h * HDIM + kseg;
            const __half* vg = Vb + (size_t)(h * HDIM + vrow) * toks + kt0 + vseg;
#pragma unroll
            for (int c = 0; c < 4; c++) {
                cpa16(ks_u + c * 16, kg + c * 8);
                cpa16(vs_u + c * 16, vg + c * 8);
            }
            cp_commit();
        }

        for (int it = 0; it < ntiles; it++) {
            const int cur = it & 1;
            cp_wait0();
            __syncthreads();
            if (it + 1 < ntiles) {
                const int kt = kt0 + (it + 1) * 64;
                const __half* kg = Kb + (size_t)(kt + krow) * D_MODEL + h * HDIM + kseg;
                const __half* vg = Vb + (size_t)(h * HDIM + vrow) * toks + kt + vseg;
                const unsigned ko = ks_u + (cur ^ 1) * KST_H * 2;
                const unsigned vo = vs_u + (cur ^ 1) * VST_H * 2;
#pragma unroll
                for (int c = 0; c < 4; c++) {
                    cpa16(ko + c * 16, kg + c * 8);
                    cpa16(vo + c * 16, vg + c * 8);
                }
                cp_commit();
            }
            const unsigned Kc_u = kmat_u + cur * KST_H * 2;
            const unsigned Vc_u = vmat_u + cur * VST_H * 2;

            // S = Q K^T
            float s[8][4];
#pragma unroll
            for (int nt = 0; nt < 8; nt++)
#pragma unroll
                for (int i = 0; i < 4; i++) s[nt][i] = 0.f;
#pragma unroll
            for (int ks = 0; ks < 8; ks++) {
#pragma unroll
                for (int ntp = 0; ntp < 4; ntp++) {
                    unsigned b[4];
                    ldsm4(b, Kc_u + (unsigned)((ntp * 16 * 136 + ks * 16) * 2));
                    mma16(s[ntp * 2],     qf[ks], b[0], b[1]);
                    mma16(s[ntp * 2 + 1], qf[ks], b[2], b[3]);
                }
            }

            // online softmax (rows r0 = w*16+g, r1 = r0+8)
            float mx0 = -1e30f, mx1 = -1e30f;
#pragma unroll
            for (int nt = 0; nt < 8; nt++) {
                mx0 = fmaxf(mx0, fmaxf(s[nt][0], s[nt][1]));
                mx1 = fmaxf(mx1, fmaxf(s[nt][2], s[nt][3]));
            }
            mx0 = fmaxf(mx0, __shfl_xor_sync(0xffffffffu, mx0, 1));
            mx0 = fmaxf(mx0, __shfl_xor_sync(0xffffffffu, mx0, 2));
            mx1 = fmaxf(mx1, __shfl_xor_sync(0xffffffffu, mx1, 1));
            mx1 = fmaxf(mx1, __shfl_xor_sync(0xffffffffu, mx1, 2));
            const float mn0 = fmaxf(mrow0, mx0), mn1 = fmaxf(mrow1, mx1);
            const float al0 = exp2f(mrow0 - mn0), al1 = exp2f(mrow1 - mn1);
            mrow0 = mn0; mrow1 = mn1;

            float sum0 = 0.f, sum1 = 0.f;
#pragma unroll
            for (int nt = 0; nt < 8; nt++) {
                float p0 = exp2f(s[nt][0] - mn0);
                float p1 = exp2f(s[nt][1] - mn0);
                float p2 = exp2f(s[nt][2] - mn1);
                float p3 = exp2f(s[nt][3] - mn1);
                sum0 += p0 + p1;
                sum1 += p2 + p3;
                Prow0[nt * 4] = h2pack(p0, p1);
                Prow1[nt * 4] = h2pack(p2, p3);
            }
            sum0 += __shfl_xor_sync(0xffffffffu, sum0, 1);
            sum0 += __shfl_xor_sync(0xffffffffu, sum0, 2);
            sum1 += __shfl_xor_sync(0xffffffffu, sum1, 1);
            sum1 += __shfl_xor_sync(0xffffffffu, sum1, 2);
            lrow0 = lrow0 * al0 + sum0;
            lrow1 = lrow1 * al1 + sum1;
#pragma unroll
            for (int nt = 0; nt < 16; nt++) {
                o[nt][0] *= al0; o[nt][1] *= al0;
                o[nt][2] *= al1; o[nt][3] *= al1;
            }
            __syncwarp();

            // O += P V  (A = P warp rows, B = Vt tiles)
#pragma unroll
            for (int ks = 0; ks < 4; ks++) {
                unsigned pa[4];
                ldsm4(pa, pmat_u + (unsigned)(ks * 32));
#pragma unroll
                for (int ntp = 0; ntp < 8; ntp++) {
                    unsigned b[4];
                    ldsm4(b, Vc_u + (unsigned)((ntp * 16 * 72 + ks * 16) * 2));
                    mma16(o[ntp * 2],     pa, b[0], b[1]);
                    mma16(o[ntp * 2 + 1], pa, b[2], b[3]);
                }
            }
            __syncwarp();
        }

        const float inv0 = 1.f / lrow0, inv1 = 1.f / lrow1;
#pragma unroll
        for (int nt = 0; nt < 16; nt++) {
            const int cc = nt * 8 + 2 * t;
            float2 v0 = make_float2(o[nt][0] * inv0, o[nt][1] * inv0);
            float2 v1 = make_float2(o[nt][2] * inv1, o[nt][3] * inv1);
            if (ph == 1) {
                float2 e0 = *(const float2*)(op0 + cc);
                float2 e1 = *(const float2*)(op1 + cc);
                v0.x += e0.x; v0.y += e0.y; v1.x += e1.x; v1.y += e1.y;
            }
            *(float2*)(op0 + cc) = v0;
            *(float2*)(op1 + cc) = v1;
        }
    }
}

// ---------------- host launcher ----------------
extern "C" void kernel_launch(void* const* d_in, const int* in_sizes, int n_in,
                              void* d_out, int out_size)
{
    (void)in_sizes; (void)n_in; (void)out_size;
    const float* x    = (const float*)d_in[0];
    const float* img  = (const float*)d_in[1];
    const float* cosr = (const float*)d_in[2];
    const float* sinr = (const float*)d_in[3];
    const float* Wq   = (const float*)d_in[4];
    const float* bq   = (const float*)d_in[5];
    const float* Wk   = (const float*)d_in[6];
    const float* bk   = (const float*)d_in[7];
    const float* Wv   = (const float*)d_in[8];
    const float* bv   = (const float*)d_in[9];
    const float* qd   = (const float*)d_in[10];
    const float* qu   = (const float*)d_in[11];
    const float* kd   = (const float*)d_in[12];
    const float* ku   = (const float*)d_in[13];
    const float* vd   = (const float*)d_in[14];
    const float* vu   = (const float*)d_in[15];
    const float* nqw  = (const float*)d_in[16];
    const float* nkw  = (const float*)d_in[17];
    const float* Wkip = (const float*)d_in[18];
    const float* Wvip = (const float*)d_in[19];
    float* out = (float*)d_out;

    __half *q, *k, *vt, *kip, *vipt, *lt;
    __half *xr, *wqr, *wkr, *wvr, *imgr, *wkipr, *wvipr, *ldr;
    float* stage;
    cudaGetSymbolAddress((void**)&q,     g_q);
    cudaGetSymbolAddress((void**)&k,     g_k);
    cudaGetSymbolAddress((void**)&vt,    g_vt);
    cudaGetSymbolAddress((void**)&kip,   g_kip);
    cudaGetSymbolAddress((void**)&vipt,  g_vipt);
    cudaGetSymbolAddress((void**)&lt,    g_lt);
    cudaGetSymbolAddress((void**)&xr,    g_xr);
    cudaGetSymbolAddress((void**)&wqr,   g_wqr);
    cudaGetSymbolAddress((void**)&wkr,   g_wkr);
    cudaGetSymbolAddress((void**)&wvr,   g_wvr);
    cudaGetSymbolAddress((void**)&imgr,  g_imgr);
    cudaGetSymbolAddress((void**)&wkipr, g_wkipr);
    cudaGetSymbolAddress((void**)&wvipr, g_wvipr);
    cudaGetSymbolAddress((void**)&ldr,   g_ldr);
    cudaGetSymbolAddress((void**)&stage, g_stage);

    const int LW = RANKN * D_MODEL;
    __half* qdr = ldr;            __half* kdr = ldr + LW;     __half* vdr = ldr + 2 * LW;
    __half* qur = ldr + 3 * LW;   __half* kur = ldr + 4 * LW; __half* vur = ldr + 5 * LW;
    float* stq = stage;
    float* stk = stage + CONDN * D_MODEL;
    float* stv = stage + 2 * CONDN * D_MODEL;

    const int GSM = 6 * 5120 * 2;   // 61440 B
    cudaFuncSetAttribute(gemm_tc<false>, cudaFuncAttributeMaxDynamicSharedMemorySize, GSM);
    cudaFuncSetAttribute(gemm_tc<true>,  cudaFuncAttributeMaxDynamicSharedMemorySize, GSM);

    // 1) fp16 rounding pre-pass (13 buffers)
    {
        R16 R;
        R.s[0]  = x;    R.d[0]  = xr;    R.n[0]  = S_TOK * D_MODEL;
        R.s[1]  = Wq;   R.d[1]  = wqr;   R.n[1]  = D_MODEL * D_MODEL;
        R.s[2]  = Wk;   R.d[2]  = wkr;   R.n[2]  = D_MODEL * D_MODEL;
        R.s[3]  = Wv;   R.d[3]  = wvr;   R.n[3]  = D_MODEL * D_MODEL;
        R.s[4]  = img;  R.d[4]  = imgr;  R.n[4]  = T_IPN * D_IPN;
        R.s[5]  = Wkip; R.d[5]  = wkipr; R.n[5]  = D_MODEL * D_IPN;
        R.s[6]  = Wvip; R.d[6]  = wvipr; R.n[6]  = D_MODEL * D_IPN;
        R.s[7]  = qd;   R.d[7]  = qdr;   R.n[7]  = LW;
        R.s[8]  = kd;   R.d[8]  = kdr;   R.n[8]  = LW;
        R.s[9]  = vd;   R.d[9]  = vdr;   R.n[9]  = LW;
        R.s[10] = qu;   R.d[10] = qur;   R.n[10] = LW;
        R.s[11] = ku;   R.d[11] = kur;   R.n[11] = LW;
        R.s[12] = vu;   R.d[12] = vur;   R.n[12] = LW;
        round_h_kernel<<<dim3(512, 13), 256>>>(R);
    }
    const __half* xcr = xr + (size_t)BLOCK_TOK * D_MODEL;

    // 2) mega GEMM: z0-2 QKV (cond rows -> fp32 stage), z3-5 LoRA-down, z6-7 IP
    {
        GemmB P;
        for (int i = 0; i < 8; i++) {
            P.tr[i] = 0; P.ldt[i] = 1; P.stoff[i] = 0; P.tokoff[i] = 0;
            P.w[i] = nullptr; P.Cst[i] = nullptr; P.accs[i] = nullptr;
        }
        P.A[0] = xr; P.A[1] = xr; P.A[2] = xr;
        P.Bm[0] = wqr; P.Bm[1] = wkr; P.Bm[2] = wvr;
        P.bias[0] = bq; P.bias[1] = bk; P.bias[2] = bv;
        P.C[0] = q;  P.C[1] = k;  P.C[2] = vt;
        P.Cst[0] = stq; P.Cst[1] = stk; P.Cst[2] = stv;
        P.w[0] = nqw; P.w[1] = nkw;
        P.M[0] = P.M[1] = P.M[2] = S_TOK;
        P.N[0] = P.N[1] = P.N[2] = D_MODEL;
        P.K[0] = P.K[1] = P.K[2] = D_MODEL;
        P.nrm[0] = 4; P.nrm[1] = 3; P.nrm[2] = 1;
        P.rowlim[0] = P.rowlim[1] = P.rowlim[2] = BLOCK_TOK;
        P.tr[2] = 1; P.ldt[2] = S_TOK;
        P.A[3] = xcr; P.A[4] = xcr; P.A[5] = xcr;
        P.Bm[3] = qdr; P.Bm[4] = kdr; P.Bm[5] = vdr;
        P.bias[3] = P.bias[4] = P.bias[5] = nullptr;
        P.C[3] = lt; P.C[4] = lt + CONDN * RANKN; P.C[5] = lt + 2 * CONDN * RANKN;
        P.M[3] = P.M[4] = P.M[5] = CONDN;
        P.N[3] = P.N[4] = P.N[5] = RANKN;
        P.K[3] = P.K[4] = P.K[5] = D_MODEL;
        P.nrm[3] = P.nrm[4] = P.nrm[5] = 1;
        P.rowlim[3] = P.rowlim[4] = P.rowlim[5] = BIGROW;
        P.A[6] = imgr; P.A[7] = imgr;
        P.Bm[6] = wkipr; P.Bm[7] = wvipr;
        P.bias[6] = P.bias[7] = nullptr;
        P.C[6] = kip; P.C[7] = vipt;
        P.M[6] = P.M[7] = T_IPN;
        P.N[6] = P.N[7] = D_MODEL;
        P.K[6] = P.K[7] = D_IPN;
        P.nrm[6] = 2; P.nrm[7] = 1;
        P.rowlim[6] = P.rowlim[7] = BIGROW;
        P.tr[7] = 1; P.ldt[7] = T_IPN;
        gemm_tc<false><<<dim3(D_MODEL / 128, S_TOK / 128, 8), 256, GSM>>>(P, cosr, sinr);
    }
    // 3) LoRA up: fp32-stage ACC + LoRA, fused norm+rope -> fp16
    {
        GemmB P;
        for (int i = 0; i < 8; i++) {
            P.A[i] = nullptr; P.Bm[i] = nullptr; P.bias[i] = nullptr; P.C[i] = nullptr;
            P.Cst[i] = nullptr; P.accs[i] = nullptr; P.w[i] = nullptr;
            P.M[i] = 0; P.N[i] = 0; P.K[i] = 32;
            P.nrm[i] = 0; P.rowlim[i] = BIGROW; P.tokoff[i] = 0;
            P.tr[i] = 0; P.ldt[i] = 1; P.stoff[i] = 0;
        }
        P.A[0] = lt; P.A[1] = lt + CONDN * RANKN; P.A[2] = lt + 2 * CONDN * RANKN;
        P.Bm[0] = qur; P.Bm[1] = kur; P.Bm[2] = vur;
        P.C[0] = q + (size_t)BLOCK_TOK * D_MODEL;
        P.C[1] = k + (size_t)BLOCK_TOK * D_MODEL;
        P.C[2] = vt;
        P.accs[0] = stq; P.accs[1] = stk; P.accs[2] = stv;
        P.w[0] = nqw; P.w[1] = nkw;
        for (int i = 0; i < 3; i++) {
            P.M[i] = CONDN; P.N[i] = D_MODEL; P.K[i] = RANKN;
            P.tokoff[i] = BLOCK_TOK;
        }
        P.nrm[0] = 4; P.nrm[1] = 3; P.nrm[2] = 1;
        P.tr[2] = 1; P.ldt[2] = S_TOK; P.stoff[2] = BLOCK_TOK;
        gemm_tc<true><<<dim3(D_MODEL / 128, CONDN / 128, 3), 256, GSM>>>(P, cosr, sinr);
    }
    // 4) fused attention: main (masked) + IP phase, fp16 m16n8k16
    {
        const int ASM = (2 * KST_H + 2 * VST_H + 128 * 72) * 2;   // 90112 B
        cudaFuncSetAttribute(attn_tc, cudaFuncAttributeMaxDynamicSharedMemorySize, ASM);
        attn_tc<<<dim3(S_TOK / 128, NHEAD), 256, ASM>>>(q, k, vt, kip, vipt, out);
    }
}